// round 12
// baseline (speedup 1.0000x reference)
#include <cuda_runtime.h>
#include <cuda_fp16.h>
#include <stdint.h>
#include <math.h>

// Problem constants (fixed by dataset: x is (16, 1024, 768), h=w=32)
#define BDIM 16
#define HDIM 32
#define WDIM 32
#define TDIM (HDIM * WDIM)          // 1024
#define CDIM 768
#define MROWS (BDIM * TDIM)         // 16384
#define QC (CDIM / 4)               // 192

#define NELEM ((size_t)MROWS * CDIM)   // 12,582,912

// WKV chunked-scan config
#define LANES (BDIM * CDIM)         // 12288
#define NCH 64
#define CHL (TDIM / NCH)            // 16

// ---------------------------------------------------------------------------
// Scratch (device globals; no allocation allowed)
// ---------------------------------------------------------------------------
__device__ __half g_a16[4][NELEM];              // 0=xk 1=xv 2=xr 3=z (fp16)
__device__ __half g_wh[4][CDIM * CDIM];         // W^T [N][K] fp16
__device__ __half g_k16[NELEM];
__device__ __half g_v16[NELEM];
__device__ __half g_sr16[NELEM];
__device__ __half g_y16[NELEM];
// wkv chunk-local states and per-chunk initial states
__device__ float g_cp[NCH * LANES], g_cq[NCH * LANES], g_co[NCH * LANES];
__device__ float g_ip[NCH * LANES], g_iq[NCH * LANES], g_io[NCH * LANES];

// ---------------------------------------------------------------------------
// PTX helpers (base sm_103-compatible: mma.sync / ldmatrix / cp.async)
// ---------------------------------------------------------------------------
__device__ __forceinline__ uint32_t smem_u32(const void* p) {
    uint32_t a;
    asm("{ .reg .u64 t; cvta.to.shared.u64 t, %1; cvt.u32.u64 %0, t; }"
        : "=r"(a) : "l"(p));
    return a;
}

__device__ __forceinline__ void ldsm4(uint32_t& r0, uint32_t& r1,
                                      uint32_t& r2, uint32_t& r3, uint32_t addr) {
    asm volatile("ldmatrix.sync.aligned.m8n8.x4.shared.b16 {%0,%1,%2,%3}, [%4];"
                 : "=r"(r0), "=r"(r1), "=r"(r2), "=r"(r3) : "r"(addr));
}

__device__ __forceinline__ void mma16816(float* c, const uint32_t* a, const uint32_t* b) {
    asm volatile(
        "mma.sync.aligned.m16n8k16.row.col.f32.f16.f16.f32 "
        "{%0,%1,%2,%3}, {%4,%5,%6,%7}, {%8,%9}, {%0,%1,%2,%3};"
        : "+f"(c[0]), "+f"(c[1]), "+f"(c[2]), "+f"(c[3])
        : "r"(a[0]), "r"(a[1]), "r"(a[2]), "r"(a[3]), "r"(b[0]), "r"(b[1]));
}

__device__ __forceinline__ void cp16(uint32_t saddr, const void* gptr) {
    asm volatile("cp.async.cg.shared.global [%0], [%1], 16;"
                 :: "r"(saddr), "l"(gptr));
}
#define CP_COMMIT() asm volatile("cp.async.commit_group;" ::: "memory")
#define CP_WAIT2()  asm volatile("cp.async.wait_group 2;" ::: "memory")

// ---------------------------------------------------------------------------
// Stage 0: weight transpose + fp16:  Wt[n][k] = W[k][n]
// ---------------------------------------------------------------------------
__global__ void wtrans_kernel(const float* __restrict__ W0, const float* __restrict__ W1,
                              const float* __restrict__ W2, const float* __restrict__ W3) {
    __shared__ float s[32][33];
    const float* W = (blockIdx.z == 0) ? W0 : (blockIdx.z == 1) ? W1
                   : (blockIdx.z == 2) ? W2 : W3;
    int n0 = blockIdx.x * 32, k0 = blockIdx.y * 32;
    int tx = threadIdx.x, ty = threadIdx.y;   // 32 x 8
#pragma unroll
    for (int i = 0; i < 4; i++) {
        int kk = ty + i * 8;
        s[kk][tx] = W[(size_t)(k0 + kk) * CDIM + n0 + tx];
    }
    __syncthreads();
#pragma unroll
    for (int i = 0; i < 4; i++) {
        int nn = ty + i * 8;
        float v = s[tx][nn];                  // = W[k0+tx][n0+nn]
        g_wh[blockIdx.z][(size_t)(n0 + nn) * CDIM + k0 + tx] = __float2half(v);
    }
}

// ---------------------------------------------------------------------------
// Stage 1: q_shift + token mixes -> fp16 (xk, xv, xr), float4 vectorized
// ---------------------------------------------------------------------------
union H4 { __half h[4]; __half2 h2[2]; uint2 u; };
union H8 { __half h[8]; __half2 h2[4]; uint4 u; };

__device__ __forceinline__ void store_h4(int sel, size_t base, float4 v) {
    H4 o;
    o.h[0] = __float2half(v.x);
    o.h[1] = __float2half(v.y);
    o.h[2] = __float2half(v.z);
    o.h[3] = __float2half(v.w);
    *(uint2*)(&g_a16[sel][base]) = o.u;
}

__global__ void shift_mix_kernel(const float* __restrict__ x,
                                 const float* __restrict__ mix_k,
                                 const float* __restrict__ mix_v,
                                 const float* __restrict__ mix_r) {
    int idx4 = blockIdx.x * blockDim.x + threadIdx.x;
    if (idx4 >= (int)(NELEM / 4)) return;
    int cq = idx4 % (CDIM / 4);
    int sp = idx4 / (CDIM / 4);
    int c  = cq * 4;
    size_t base = (size_t)sp * CDIM + c;
    int wq = sp % WDIM;
    int hq = (sp / WDIM) % HDIM;

    float4 xx = make_float4(0.f, 0.f, 0.f, 0.f);
    int g = c / QC;
    if (g == 0) {
        if (wq > 0)         xx = *(const float4*)(x + base - CDIM);
    } else if (g == 1) {
        if (wq < WDIM - 1)  xx = *(const float4*)(x + base + CDIM);
    } else if (g == 2) {
        if (hq > 0)         xx = *(const float4*)(x + base - (size_t)WDIM * CDIM);
    } else {
        if (hq < HDIM - 1)  xx = *(const float4*)(x + base + (size_t)WDIM * CDIM);
    }

    float4 xc = *(const float4*)(x + base);
    float4 mk = *(const float4*)(mix_k + c);
    float4 mv = *(const float4*)(mix_v + c);
    float4 mr = *(const float4*)(mix_r + c);

    float4 vk, vv, vr;
    vk.x = xc.x * mk.x + xx.x * (1.f - mk.x);
    vk.y = xc.y * mk.y + xx.y * (1.f - mk.y);
    vk.z = xc.z * mk.z + xx.z * (1.f - mk.z);
    vk.w = xc.w * mk.w + xx.w * (1.f - mk.w);
    vv.x = xc.x * mv.x + xx.x * (1.f - mv.x);
    vv.y = xc.y * mv.y + xx.y * (1.f - mv.y);
    vv.z = xc.z * mv.z + xx.z * (1.f - mv.z);
    vv.w = xc.w * mv.w + xx.w * (1.f - mv.w);
    vr.x = xc.x * mr.x + xx.x * (1.f - mr.x);
    vr.y = xc.y * mr.y + xx.y * (1.f - mr.y);
    vr.z = xc.z * mr.z + xx.z * (1.f - mr.z);
    vr.w = xc.w * mr.w + xx.w * (1.f - mr.w);

    store_h4(0, base, vk);
    store_h4(1, base, vv);
    store_h4(2, base, vr);
}

// ---------------------------------------------------------------------------
// Stage 2/5: fp16 tensor-core GEMM via mma.sync (single pass).
// CTA tile 128x128, 8 warps (2x4 -> 64x32 each), BK=32, 4-stage cp.async,
// XOR-swizzled 64B-pitch smem, one __syncthreads per k-iter, 2 CTAs/SM.
// (FROZEN configuration — round-7 optimum.)
// ---------------------------------------------------------------------------
#define TILEB 8192                         // 128 rows * 64B
#define STAGEB (2 * TILEB)                 // 16384: [A | Wh]
#define NSTAGE 4
#define SM_GEMM (NSTAGE * STAGEB)          // 65536

// smem byte offset for (row, 16B-chunk) with XOR swizzle
__device__ __forceinline__ uint32_t swz_off(int row, int cc) {
    return (uint32_t)(row * 64 + ((cc ^ ((row >> 1) & 3)) << 4));
}

__global__ __launch_bounds__(256, 2)
void tc_gemm_kernel(int aSel, float* __restrict__ cOut) {
    extern __shared__ char smem[];
    const uint32_t sb = smem_u32(smem);
    const int tid = threadIdx.x;
    const int w = tid >> 5, l = tid & 31;
    const int wm = w >> 2, wn = w & 3;

    const int s = (aSel < 0) ? (int)blockIdx.z : aSel;

    const __half* __restrict__ A  = g_a16[s];
    const __half* __restrict__ Wh = g_wh[s];

    const int mrow0 = blockIdx.y * 128;
    const int ncol0 = blockIdx.x * 128;

    float acc[4][4][4];
#pragma unroll
    for (int i = 0; i < 4; i++)
#pragma unroll
        for (int j = 0; j < 4; j++)
#pragma unroll
            for (int q = 0; q < 4; q++) acc[i][j][q] = 0.0f;

    auto issue = [&](int kc, int st) {
        if (kc < 24) {
            uint32_t s0 = sb + st * STAGEB;
#pragma unroll
            for (int j = 0; j < 2; j++) {
                int id = tid + j * 256;          // 0..511
                int row = id >> 2, cc = id & 3;
                size_t gA = (size_t)(mrow0 + row) * CDIM + kc * 32 + cc * 8;
                size_t gB = (size_t)(ncol0 + row) * CDIM + kc * 32 + cc * 8;
                uint32_t so = swz_off(row, cc);
                cp16(s0 + 0 * TILEB + so, A  + gA);
                cp16(s0 + 1 * TILEB + so, Wh + gB);
            }
        }
        CP_COMMIT();
    };

    issue(0, 0); issue(1, 1); issue(2, 2);

    // per-lane ldmatrix row / chunk invariants
    const int aRow = wm * 64 + (l & 15);
    const int aC0  = l >> 4;                    // 0..1
    const int aSwz = (aRow >> 1) & 3;
    const int bRow = wn * 32 + ((l & 7) | ((l >> 4) << 3));
    const int bC0  = (l >> 3) & 1;
    const int bSwz = (bRow >> 1) & 3;

    for (int kc = 0; kc < 24; kc++) {
        int st = kc & 3;
        CP_WAIT2();
        __syncthreads();
        issue(kc + 3, (kc + 3) & 3);
        uint32_t s0 = sb + st * STAGEB;
#pragma unroll
        for (int ks = 0; ks < 2; ks++) {
            uint32_t a[4][4], bh[2][4];
            uint32_t aA = s0 + aRow * 64 + (((aC0 + ks * 2) ^ aSwz) << 4);
            uint32_t bA = s0 + TILEB + bRow * 64 + (((bC0 + ks * 2) ^ bSwz) << 4);
#pragma unroll
            for (int am = 0; am < 4; am++)
                ldsm4(a[am][0], a[am][1], a[am][2], a[am][3],
                      aA + am * 1024);                       // +16 rows
#pragma unroll
            for (int bn = 0; bn < 2; bn++)
                ldsm4(bh[bn][0], bh[bn][1], bh[bn][2], bh[bn][3],
                      bA + bn * 1024);
#pragma unroll
            for (int am = 0; am < 4; am++)
#pragma unroll
                for (int an = 0; an < 4; an++)
                    mma16816(acc[am][an], a[am], &bh[an >> 1][(an & 1) * 2]);
        }
    }

    // Epilogue. s==0/1/2 -> fp16 k/v/sr (sigmoid for s==2); s==3 -> fp32 out.
    if (s <= 2) {
        __half* __restrict__ Ch = (s == 0) ? g_k16 : (s == 1) ? g_v16 : g_sr16;
        const bool sig = (s == 2);
#pragma unroll
        for (int am = 0; am < 4; am++) {
            int r0 = mrow0 + wm * 64 + am * 16 + (l >> 2);
#pragma unroll
            for (int an = 0; an < 4; an++) {
                int cc = ncol0 + wn * 32 + an * 8 + (l & 3) * 2;
                float v0 = acc[am][an][0], v1 = acc[am][an][1];
                float v2 = acc[am][an][2], v3 = acc[am][an][3];
                if (sig) {
                    v0 = 1.0f / (1.0f + __expf(-v0));
                    v1 = 1.0f / (1.0f + __expf(-v1));
                    v2 = 1.0f / (1.0f + __expf(-v2));
                    v3 = 1.0f / (1.0f + __expf(-v3));
                }
                *(__half2*)(Ch + (size_t)r0 * CDIM + cc) =
                    __floats2half2_rn(v0, v1);
                *(__half2*)(Ch + (size_t)(r0 + 8) * CDIM + cc) =
                    __floats2half2_rn(v2, v3);
            }
        }
    } else {
#pragma unroll
        for (int am = 0; am < 4; am++) {
            int r0 = mrow0 + wm * 64 + am * 16 + (l >> 2);
#pragma unroll
            for (int an = 0; an < 4; an++) {
                int cc = ncol0 + wn * 32 + an * 8 + (l & 3) * 2;
                *(float2*)(cOut + (size_t)r0 * CDIM + cc) =
                    make_float2(acc[am][an][0], acc[am][an][1]);
                *(float2*)(cOut + (size_t)(r0 + 8) * CDIM + cc) =
                    make_float2(acc[am][an][2], acc[am][an][3]);
            }
        }
    }
}

// ---------------------------------------------------------------------------
// Stage 3: WKV as 3-phase chunked scan (64 chunks of 16 steps), fp16 k/v,
// ILP-2: each thread runs TWO adjacent channels' chains via __half2 loads.
// ---------------------------------------------------------------------------
__device__ __forceinline__ void wkv_update(float& p, float& q, float& o,
                                           float w, float kt, float vt) {
    float wo  = w + o;
    float no2 = fmaxf(wo, kt);
    float A2  = __expf(wo - no2);
    float B2  = __expf(kt - no2);
    p = A2 * p + B2 * vt;
    q = A2 * q + B2;
    o = no2;
}

#define CD2 (CDIM / 2)
#define LANES2 (LANES / 2)

__global__ void wkv_p1_kernel(const float* __restrict__ spatial_decay) {
    int idx = blockIdx.x * blockDim.x + threadIdx.x;   // 0..NCH*LANES2-1
    if (idx >= NCH * LANES2) return;
    int chunk = idx / LANES2;
    int l2    = idx % LANES2;
    int c2 = l2 % CD2, b = l2 / CD2;
    int c = c2 * 2;
    const float inv_t = 1.0f / (float)TDIM;
    float w0 = spatial_decay[c]     * inv_t;
    float w1 = spatial_decay[c + 1] * inv_t;

    const __half2* kp = (const __half2*)(g_k16 + ((size_t)b * TDIM + chunk * CHL) * CDIM) + c2;
    const __half2* vp = (const __half2*)(g_v16 + ((size_t)b * TDIM + chunk * CHL) * CDIM) + c2;

    float p0 = 0.f, q0 = 0.f, o0 = -1e38f;
    float p1 = 0.f, q1 = 0.f, o1 = -1e38f;
#pragma unroll 4
    for (int t = 0; t < CHL; t++) {
        float2 kf = __half22float2(kp[(size_t)t * CD2]);
        float2 vf = __half22float2(vp[(size_t)t * CD2]);
        wkv_update(p0, q0, o0, w0, kf.x, vf.x);
        wkv_update(p1, q1, o1, w1, kf.y, vf.y);
    }

    int i0 = chunk * LANES + b * CDIM + c;
    g_cp[i0] = p0; g_cq[i0] = q0; g_co[i0] = o0;
    g_cp[i0 + 1] = p1; g_cq[i0 + 1] = q1; g_co[i0 + 1] = o1;
}

__global__ void wkv_p2_kernel(const float* __restrict__ spatial_decay) {
    int lane = blockIdx.x * blockDim.x + threadIdx.x;
    if (lane >= LANES) return;
    int c = lane % CDIM;
    float wL = spatial_decay[c] * (1.0f / (float)TDIM) * (float)CHL;

    float p = 0.f, q = 0.f, o = -1e38f;
#pragma unroll 8
    for (int j = 0; j < NCH; j++) {
        int idx = j * LANES + lane;
        g_ip[idx] = p; g_iq[idx] = q; g_io[idx] = o;
        float cp = g_cp[idx], cq = g_cq[idx], co = g_co[idx];
        float ow = o + wL;
        float no = fmaxf(ow, co);
        float A = __expf(ow - no);
        float B = __expf(co - no);
        p = A * p + B * cp;
        q = A * q + B * cq;
        o = no;
    }
}

__global__ void wkv_p3_kernel(const float* __restrict__ spatial_decay,
                              const float* __restrict__ spatial_first) {
    int idx = blockIdx.x * blockDim.x + threadIdx.x;
    if (idx >= NCH * LANES2) return;
    int chunk = idx / LANES2;
    int l2    = idx % LANES2;
    int c2 = l2 % CD2, b = l2 / CD2;
    int c = c2 * 2;
    const float inv_t = 1.0f / (float)TDIM;
    float w0 = spatial_decay[c]     * inv_t;
    float w1 = spatial_decay[c + 1] * inv_t;
    float u0 = spatial_first[c]     * inv_t;
    float u1 = spatial_first[c + 1] * inv_t;

    const __half2* kp = (const __half2*)(g_k16 + ((size_t)b * TDIM + chunk * CHL) * CDIM) + c2;
    const __half2* vp = (const __half2*)(g_v16 + ((size_t)b * TDIM + chunk * CHL) * CDIM) + c2;
    __half2*       yp = (__half2*)(g_y16 + ((size_t)b * TDIM + chunk * CHL) * CDIM) + c2;

    int i0 = chunk * LANES + b * CDIM + c;
    float p0 = g_ip[i0], q0 = g_iq[i0], o0 = g_io[i0];
    float p1 = g_ip[i0 + 1], q1 = g_iq[i0 + 1], o1 = g_io[i0 + 1];

#pragma unroll 4
    for (int t = 0; t < CHL; t++) {
        float2 kf = __half22float2(kp[(size_t)t * CD2]);
        float2 vf = __half22float2(vp[(size_t)t * CD2]);

        float uk0 = u0 + kf.x;
        float no0 = fmaxf(o0, uk0);
        float Aa0 = __expf(o0 - no0);
        float Bb0 = __expf(uk0 - no0);
        float y0 = __fdividef(Aa0 * p0 + Bb0 * vf.x, Aa0 * q0 + Bb0);

        float uk1 = u1 + kf.y;
        float no1 = fmaxf(o1, uk1);
        float Aa1 = __expf(o1 - no1);
        float Bb1 = __expf(uk1 - no1);
        float y1 = __fdividef(Aa1 * p1 + Bb1 * vf.y, Aa1 * q1 + Bb1);

        yp[(size_t)t * CD2] = __floats2half2_rn(y0, y1);

        wkv_update(p0, q0, o0, w0, kf.x, vf.x);
        wkv_update(p1, q1, o1, w1, kf.y, vf.y);
    }
}

// ---------------------------------------------------------------------------
// Stage 4: layernorm(y) * sigmoid_r -> z (fp16). Warp per row, 8 rows/block.
// ---------------------------------------------------------------------------
__global__ __launch_bounds__(256)
void ln_gate_kernel(const float* __restrict__ ln_g,
                    const float* __restrict__ ln_b) {
    int wid  = threadIdx.x >> 5;
    int lane = threadIdx.x & 31;
    int row  = blockIdx.x * 8 + wid;
    size_t rbase = (size_t)row * CDIM;
    const uint4* yrow  = (const uint4*)(g_y16  + rbase);
    const uint4* srrow = (const uint4*)(g_sr16 + rbase);

    // 3 x uint4 = 24 halves per lane
    H8 y8[3];
    float yf[24];
    float s = 0.f;
#pragma unroll
    for (int i = 0; i < 3; i++) {
        y8[i].u = yrow[lane + i * 32];
#pragma unroll
        for (int j = 0; j < 4; j++) {
            float2 f2 = __half22float2(y8[i].h2[j]);
            yf[i * 8 + j * 2]     = f2.x;
            yf[i * 8 + j * 2 + 1] = f2.y;
            s += f2.x + f2.y;
        }
    }
#pragma unroll
    for (int off = 16; off > 0; off >>= 1)
        s += __shfl_xor_sync(0xffffffffu, s, off);
    float mu = s * (1.0f / CDIM);

    float ss = 0.f;
#pragma unroll
    for (int i = 0; i < 24; i++) {
        float d = yf[i] - mu;
        ss += d * d;
    }
#pragma unroll
    for (int off = 16; off > 0; off >>= 1)
        ss += __shfl_xor_sync(0xffffffffu, ss, off);
    float rstd = rsqrtf(ss * (1.0f / CDIM) + 1e-5f);

    uint4* zrow = (uint4*)(g_a16[3] + rbase);
#pragma unroll
    for (int i = 0; i < 3; i++) {
        int c0 = (lane + i * 32) * 8;
        H8 sr8; sr8.u = srrow[lane + i * 32];
        H8 zo;
#pragma unroll
        for (int j = 0; j < 4; j++) {
            float2 sr2 = __half22float2(sr8.h2[j]);
            int c = c0 + j * 2;
            float z0 = sr2.x * ((yf[i * 8 + j * 2]     - mu) * rstd * ln_g[c]     + ln_b[c]);
            float z1 = sr2.y * ((yf[i * 8 + j * 2 + 1] - mu) * rstd * ln_g[c + 1] + ln_b[c + 1]);
            zo.h2[j] = __floats2half2_rn(z0, z1);
        }
        zrow[lane + i * 32] = zo.u;
    }
}

// ---------------------------------------------------------------------------
// Launch
// ---------------------------------------------------------------------------
extern "C" void kernel_launch(void* const* d_in, const int* in_sizes, int n_in,
                              void* d_out, int out_size) {
    const float* x   = (const float*)d_in[0];
    const float* sd  = (const float*)d_in[3];
    const float* sf  = (const float*)d_in[4];
    const float* mk  = (const float*)d_in[5];
    const float* mv  = (const float*)d_in[6];
    const float* mr  = (const float*)d_in[7];
    const float* Wk  = (const float*)d_in[8];
    const float* Wv  = (const float*)d_in[9];
    const float* Wr  = (const float*)d_in[10];
    const float* Wo  = (const float*)d_in[11];
    const float* lg  = (const float*)d_in[12];
    const float* lb  = (const float*)d_in[13];
    float* out = (float*)d_out;

    cudaFuncSetAttribute(tc_gemm_kernel,
                         cudaFuncAttributeMaxDynamicSharedMemorySize, SM_GEMM);

    // 0. transpose weights -> fp16
    {
        dim3 blk(32, 8);
        dim3 grd(CDIM / 32, CDIM / 32, 4);
        wtrans_kernel<<<grd, blk>>>(Wk, Wv, Wr, Wo);
    }

    // 1. q_shift + mixes -> fp16
    {
        int n4 = (int)(NELEM / 4);
        shift_mix_kernel<<<(n4 + 255) / 256, 256>>>(x, mk, mv, mr);
    }

    // 2. fused k / v / sr GEMMs (z = 0,1,2)
    {
        dim3 gg(CDIM / 128, MROWS / 128, 3);
        tc_gemm_kernel<<<gg, 256, SM_GEMM>>>(-1, nullptr);
    }

    // 3. WKV chunked scan (fp16 k/v, ILP-2, 64 chunks of 16)
    wkv_p1_kernel<<<(NCH * LANES2) / 256, 256>>>(sd);
    wkv_p2_kernel<<<(LANES + 255) / 256, 256>>>(sd);
    wkv_p3_kernel<<<(NCH * LANES2) / 256, 256>>>(sd, sf);

    // 4. layernorm + gate -> z (fp16)
    ln_gate_kernel<<<MROWS / 8, 256>>>(lg, lb);

    // 5. output projection -> d_out
    {
        dim3 gg(CDIM / 128, MROWS / 128, 1);
        tc_gemm_kernel<<<gg, 256, SM_GEMM>>>(3, out);
    }
}

// round 13
// speedup vs baseline: 1.0343x; 1.0343x over previous
#include <cuda_runtime.h>
#include <cuda_fp16.h>
#include <stdint.h>
#include <math.h>

// Problem constants (fixed by dataset: x is (16, 1024, 768), h=w=32)
#define BDIM 16
#define HDIM 32
#define WDIM 32
#define TDIM (HDIM * WDIM)          // 1024
#define CDIM 768
#define MROWS (BDIM * TDIM)         // 16384
#define QC (CDIM / 4)               // 192

#define NELEM ((size_t)MROWS * CDIM)   // 12,582,912

// WKV chunked-scan config (FROZEN: round-10 optimum)
#define LANES (BDIM * CDIM)         // 12288
#define NCH 32
#define CHL (TDIM / NCH)            // 32

// ---------------------------------------------------------------------------
// Scratch (device globals; no allocation allowed)
// ---------------------------------------------------------------------------
__device__ __half g_a16[4][NELEM];              // 0=xk 1=xv 2=xr 3=z (fp16)
__device__ __half g_wh[4][CDIM * CDIM];         // W^T [N][K] fp16
__device__ __half g_k16[NELEM];
__device__ __half g_v16[NELEM];
__device__ __half g_sr16[NELEM];
__device__ __half g_y16[NELEM];
// wkv chunk-local states and per-chunk initial states
__device__ float g_cp[NCH * LANES], g_cq[NCH * LANES], g_co[NCH * LANES];
__device__ float g_ip[NCH * LANES], g_iq[NCH * LANES], g_io[NCH * LANES];

// ---------------------------------------------------------------------------
// PTX helpers (base sm_103-compatible: mma.sync / ldmatrix / cp.async)
// ---------------------------------------------------------------------------
__device__ __forceinline__ uint32_t smem_u32(const void* p) {
    uint32_t a;
    asm("{ .reg .u64 t; cvta.to.shared.u64 t, %1; cvt.u32.u64 %0, t; }"
        : "=r"(a) : "l"(p));
    return a;
}

__device__ __forceinline__ void ldsm4(uint32_t& r0, uint32_t& r1,
                                      uint32_t& r2, uint32_t& r3, uint32_t addr) {
    asm volatile("ldmatrix.sync.aligned.m8n8.x4.shared.b16 {%0,%1,%2,%3}, [%4];"
                 : "=r"(r0), "=r"(r1), "=r"(r2), "=r"(r3) : "r"(addr));
}

__device__ __forceinline__ void mma16816(float* c, const uint32_t* a, const uint32_t* b) {
    asm volatile(
        "mma.sync.aligned.m16n8k16.row.col.f32.f16.f16.f32 "
        "{%0,%1,%2,%3}, {%4,%5,%6,%7}, {%8,%9}, {%0,%1,%2,%3};"
        : "+f"(c[0]), "+f"(c[1]), "+f"(c[2]), "+f"(c[3])
        : "r"(a[0]), "r"(a[1]), "r"(a[2]), "r"(a[3]), "r"(b[0]), "r"(b[1]));
}

__device__ __forceinline__ void cp16(uint32_t saddr, const void* gptr) {
    asm volatile("cp.async.cg.shared.global [%0], [%1], 16;"
                 :: "r"(saddr), "l"(gptr));
}
#define CP_COMMIT() asm volatile("cp.async.commit_group;" ::: "memory")
#define CP_WAIT2()  asm volatile("cp.async.wait_group 2;" ::: "memory")

// ---------------------------------------------------------------------------
// Stage 0: weight transpose + fp16:  Wt[n][k] = W[k][n]
// ---------------------------------------------------------------------------
__global__ void wtrans_kernel(const float* __restrict__ W0, const float* __restrict__ W1,
                              const float* __restrict__ W2, const float* __restrict__ W3) {
    __shared__ float s[32][33];
    const float* W = (blockIdx.z == 0) ? W0 : (blockIdx.z == 1) ? W1
                   : (blockIdx.z == 2) ? W2 : W3;
    int n0 = blockIdx.x * 32, k0 = blockIdx.y * 32;
    int tx = threadIdx.x, ty = threadIdx.y;   // 32 x 8
#pragma unroll
    for (int i = 0; i < 4; i++) {
        int kk = ty + i * 8;
        s[kk][tx] = W[(size_t)(k0 + kk) * CDIM + n0 + tx];
    }
    __syncthreads();
#pragma unroll
    for (int i = 0; i < 4; i++) {
        int nn = ty + i * 8;
        float v = s[tx][nn];                  // = W[k0+tx][n0+nn]
        g_wh[blockIdx.z][(size_t)(n0 + nn) * CDIM + k0 + tx] = __float2half(v);
    }
}

// ---------------------------------------------------------------------------
// Stage 1: q_shift + token mixes -> fp16 (xk, xv, xr), float4 vectorized
// ---------------------------------------------------------------------------
union H4 { __half h[4]; __half2 h2[2]; uint2 u; };
union H8 { __half h[8]; __half2 h2[4]; uint4 u; };

__device__ __forceinline__ void store_h4(int sel, size_t base, float4 v) {
    H4 o;
    o.h[0] = __float2half(v.x);
    o.h[1] = __float2half(v.y);
    o.h[2] = __float2half(v.z);
    o.h[3] = __float2half(v.w);
    *(uint2*)(&g_a16[sel][base]) = o.u;
}

__global__ void shift_mix_kernel(const float* __restrict__ x,
                                 const float* __restrict__ mix_k,
                                 const float* __restrict__ mix_v,
                                 const float* __restrict__ mix_r) {
    int idx4 = blockIdx.x * blockDim.x + threadIdx.x;
    if (idx4 >= (int)(NELEM / 4)) return;
    int cq = idx4 % (CDIM / 4);
    int sp = idx4 / (CDIM / 4);
    int c  = cq * 4;
    size_t base = (size_t)sp * CDIM + c;
    int wq = sp % WDIM;
    int hq = (sp / WDIM) % HDIM;

    float4 xx = make_float4(0.f, 0.f, 0.f, 0.f);
    int g = c / QC;
    if (g == 0) {
        if (wq > 0)         xx = *(const float4*)(x + base - CDIM);
    } else if (g == 1) {
        if (wq < WDIM - 1)  xx = *(const float4*)(x + base + CDIM);
    } else if (g == 2) {
        if (hq > 0)         xx = *(const float4*)(x + base - (size_t)WDIM * CDIM);
    } else {
        if (hq < HDIM - 1)  xx = *(const float4*)(x + base + (size_t)WDIM * CDIM);
    }

    float4 xc = *(const float4*)(x + base);
    float4 mk = *(const float4*)(mix_k + c);
    float4 mv = *(const float4*)(mix_v + c);
    float4 mr = *(const float4*)(mix_r + c);

    float4 vk, vv, vr;
    vk.x = xc.x * mk.x + xx.x * (1.f - mk.x);
    vk.y = xc.y * mk.y + xx.y * (1.f - mk.y);
    vk.z = xc.z * mk.z + xx.z * (1.f - mk.z);
    vk.w = xc.w * mk.w + xx.w * (1.f - mk.w);
    vv.x = xc.x * mv.x + xx.x * (1.f - mv.x);
    vv.y = xc.y * mv.y + xx.y * (1.f - mv.y);
    vv.z = xc.z * mv.z + xx.z * (1.f - mv.z);
    vv.w = xc.w * mv.w + xx.w * (1.f - mv.w);
    vr.x = xc.x * mr.x + xx.x * (1.f - mr.x);
    vr.y = xc.y * mr.y + xx.y * (1.f - mr.y);
    vr.z = xc.z * mr.z + xx.z * (1.f - mr.z);
    vr.w = xc.w * mr.w + xx.w * (1.f - mr.w);

    store_h4(0, base, vk);
    store_h4(1, base, vv);
    store_h4(2, base, vr);
}

// ---------------------------------------------------------------------------
// Stage 2/5: fp16 tensor-core GEMM via mma.sync (single pass).
// CTA tile 128x128, 8 warps (2x4 -> 64x32 each), BK=32, 4-stage cp.async,
// XOR-swizzled 64B-pitch smem, one __syncthreads per k-iter, 2 CTAs/SM.
// (FROZEN configuration — round-7 optimum.)
// ---------------------------------------------------------------------------
#define TILEB 8192                         // 128 rows * 64B
#define STAGEB (2 * TILEB)                 // 16384: [A | Wh]
#define NSTAGE 4
#define SM_GEMM (NSTAGE * STAGEB)          // 65536

// smem byte offset for (row, 16B-chunk) with XOR swizzle
__device__ __forceinline__ uint32_t swz_off(int row, int cc) {
    return (uint32_t)(row * 64 + ((cc ^ ((row >> 1) & 3)) << 4));
}

__global__ __launch_bounds__(256, 2)
void tc_gemm_kernel(int aSel, float* __restrict__ cOut) {
    extern __shared__ char smem[];
    const uint32_t sb = smem_u32(smem);
    const int tid = threadIdx.x;
    const int w = tid >> 5, l = tid & 31;
    const int wm = w >> 2, wn = w & 3;

    const int s = (aSel < 0) ? (int)blockIdx.z : aSel;

    const __half* __restrict__ A  = g_a16[s];
    const __half* __restrict__ Wh = g_wh[s];

    const int mrow0 = blockIdx.y * 128;
    const int ncol0 = blockIdx.x * 128;

    float acc[4][4][4];
#pragma unroll
    for (int i = 0; i < 4; i++)
#pragma unroll
        for (int j = 0; j < 4; j++)
#pragma unroll
            for (int q = 0; q < 4; q++) acc[i][j][q] = 0.0f;

    auto issue = [&](int kc, int st) {
        if (kc < 24) {
            uint32_t s0 = sb + st * STAGEB;
#pragma unroll
            for (int j = 0; j < 2; j++) {
                int id = tid + j * 256;          // 0..511
                int row = id >> 2, cc = id & 3;
                size_t gA = (size_t)(mrow0 + row) * CDIM + kc * 32 + cc * 8;
                size_t gB = (size_t)(ncol0 + row) * CDIM + kc * 32 + cc * 8;
                uint32_t so = swz_off(row, cc);
                cp16(s0 + 0 * TILEB + so, A  + gA);
                cp16(s0 + 1 * TILEB + so, Wh + gB);
            }
        }
        CP_COMMIT();
    };

    issue(0, 0); issue(1, 1); issue(2, 2);

    // per-lane ldmatrix row / chunk invariants
    const int aRow = wm * 64 + (l & 15);
    const int aC0  = l >> 4;                    // 0..1
    const int aSwz = (aRow >> 1) & 3;
    const int bRow = wn * 32 + ((l & 7) | ((l >> 4) << 3));
    const int bC0  = (l >> 3) & 1;
    const int bSwz = (bRow >> 1) & 3;

    for (int kc = 0; kc < 24; kc++) {
        int st = kc & 3;
        CP_WAIT2();
        __syncthreads();
        issue(kc + 3, (kc + 3) & 3);
        uint32_t s0 = sb + st * STAGEB;
#pragma unroll
        for (int ks = 0; ks < 2; ks++) {
            uint32_t a[4][4], bh[2][4];
            uint32_t aA = s0 + aRow * 64 + (((aC0 + ks * 2) ^ aSwz) << 4);
            uint32_t bA = s0 + TILEB + bRow * 64 + (((bC0 + ks * 2) ^ bSwz) << 4);
#pragma unroll
            for (int am = 0; am < 4; am++)
                ldsm4(a[am][0], a[am][1], a[am][2], a[am][3],
                      aA + am * 1024);                       // +16 rows
#pragma unroll
            for (int bn = 0; bn < 2; bn++)
                ldsm4(bh[bn][0], bh[bn][1], bh[bn][2], bh[bn][3],
                      bA + bn * 1024);
#pragma unroll
            for (int am = 0; am < 4; am++)
#pragma unroll
                for (int an = 0; an < 4; an++)
                    mma16816(acc[am][an], a[am], &bh[an >> 1][(an & 1) * 2]);
        }
    }

    // Epilogue. s==0/1/2 -> fp16 k/v/sr (sigmoid for s==2); s==3 -> fp32 out.
    if (s <= 2) {
        __half* __restrict__ Ch = (s == 0) ? g_k16 : (s == 1) ? g_v16 : g_sr16;
        const bool sig = (s == 2);
#pragma unroll
        for (int am = 0; am < 4; am++) {
            int r0 = mrow0 + wm * 64 + am * 16 + (l >> 2);
#pragma unroll
            for (int an = 0; an < 4; an++) {
                int cc = ncol0 + wn * 32 + an * 8 + (l & 3) * 2;
                float v0 = acc[am][an][0], v1 = acc[am][an][1];
                float v2 = acc[am][an][2], v3 = acc[am][an][3];
                if (sig) {
                    v0 = 1.0f / (1.0f + __expf(-v0));
                    v1 = 1.0f / (1.0f + __expf(-v1));
                    v2 = 1.0f / (1.0f + __expf(-v2));
                    v3 = 1.0f / (1.0f + __expf(-v3));
                }
                *(__half2*)(Ch + (size_t)r0 * CDIM + cc) =
                    __floats2half2_rn(v0, v1);
                *(__half2*)(Ch + (size_t)(r0 + 8) * CDIM + cc) =
                    __floats2half2_rn(v2, v3);
            }
        }
    } else {
#pragma unroll
        for (int am = 0; am < 4; am++) {
            int r0 = mrow0 + wm * 64 + am * 16 + (l >> 2);
#pragma unroll
            for (int an = 0; an < 4; an++) {
                int cc = ncol0 + wn * 32 + an * 8 + (l & 3) * 2;
                *(float2*)(cOut + (size_t)r0 * CDIM + cc) =
                    make_float2(acc[am][an][0], acc[am][an][1]);
                *(float2*)(cOut + (size_t)(r0 + 8) * CDIM + cc) =
                    make_float2(acc[am][an][2], acc[am][an][3]);
            }
        }
    }
}

// ---------------------------------------------------------------------------
// Stage 3: WKV as 3-phase chunked scan (32 chunks of 32 steps), fp16 k/v,
// ILP-2 over channel pairs, float2-vectorized state I/O.
// ---------------------------------------------------------------------------
__device__ __forceinline__ void wkv_update(float& p, float& q, float& o,
                                           float w, float kt, float vt) {
    float wo  = w + o;
    float no2 = fmaxf(wo, kt);
    float A2  = __expf(wo - no2);
    float B2  = __expf(kt - no2);
    p = A2 * p + B2 * vt;
    q = A2 * q + B2;
    o = no2;
}

#define CD2 (CDIM / 2)
#define LANES2 (LANES / 2)

__global__ void wkv_p1_kernel(const float* __restrict__ spatial_decay) {
    int idx = blockIdx.x * blockDim.x + threadIdx.x;   // 0..NCH*LANES2-1
    if (idx >= NCH * LANES2) return;
    int chunk = idx / LANES2;
    int l2    = idx % LANES2;
    int c2 = l2 % CD2, b = l2 / CD2;
    int c = c2 * 2;
    const float inv_t = 1.0f / (float)TDIM;
    float w0 = spatial_decay[c]     * inv_t;
    float w1 = spatial_decay[c + 1] * inv_t;

    const __half2* kp = (const __half2*)(g_k16 + ((size_t)b * TDIM + chunk * CHL) * CDIM) + c2;
    const __half2* vp = (const __half2*)(g_v16 + ((size_t)b * TDIM + chunk * CHL) * CDIM) + c2;

    float p0 = 0.f, q0 = 0.f, o0 = -1e38f;
    float p1 = 0.f, q1 = 0.f, o1 = -1e38f;
#pragma unroll 4
    for (int t = 0; t < CHL; t++) {
        float2 kf = __half22float2(kp[(size_t)t * CD2]);
        float2 vf = __half22float2(vp[(size_t)t * CD2]);
        wkv_update(p0, q0, o0, w0, kf.x, vf.x);
        wkv_update(p1, q1, o1, w1, kf.y, vf.y);
    }

    int i0 = chunk * LANES + b * CDIM + c;
    *(float2*)(g_cp + i0) = make_float2(p0, p1);
    *(float2*)(g_cq + i0) = make_float2(q0, q1);
    *(float2*)(g_co + i0) = make_float2(o0, o1);
}

__global__ void wkv_p2_kernel(const float* __restrict__ spatial_decay) {
    int lane = blockIdx.x * blockDim.x + threadIdx.x;
    if (lane >= LANES) return;
    int c = lane % CDIM;
    float wL = spatial_decay[c] * (1.0f / (float)TDIM) * (float)CHL;

    float p = 0.f, q = 0.f, o = -1e38f;
#pragma unroll
    for (int j = 0; j < NCH; j++) {
        int idx = j * LANES + lane;
        g_ip[idx] = p; g_iq[idx] = q; g_io[idx] = o;
        float cp = g_cp[idx], cq = g_cq[idx], co = g_co[idx];
        float ow = o + wL;
        float no = fmaxf(ow, co);
        float A = __expf(ow - no);
        float B = __expf(co - no);
        p = A * p + B * cp;
        q = A * q + B * cq;
        o = no;
    }
}

__global__ void wkv_p3_kernel(const float* __restrict__ spatial_decay,
                              const float* __restrict__ spatial_first) {
    int idx = blockIdx.x * blockDim.x + threadIdx.x;
    if (idx >= NCH * LANES2) return;
    int chunk = idx / LANES2;
    int l2    = idx % LANES2;
    int c2 = l2 % CD2, b = l2 / CD2;
    int c = c2 * 2;
    const float inv_t = 1.0f / (float)TDIM;
    float w0 = spatial_decay[c]     * inv_t;
    float w1 = spatial_decay[c + 1] * inv_t;
    float u0 = spatial_first[c]     * inv_t;
    float u1 = spatial_first[c + 1] * inv_t;

    const __half2* kp = (const __half2*)(g_k16 + ((size_t)b * TDIM + chunk * CHL) * CDIM) + c2;
    const __half2* vp = (const __half2*)(g_v16 + ((size_t)b * TDIM + chunk * CHL) * CDIM) + c2;
    __half2*       yp = (__half2*)(g_y16 + ((size_t)b * TDIM + chunk * CHL) * CDIM) + c2;

    int i0 = chunk * LANES + b * CDIM + c;
    float2 pp = *(const float2*)(g_ip + i0);
    float2 qq = *(const float2*)(g_iq + i0);
    float2 oo = *(const float2*)(g_io + i0);
    float p0 = pp.x, q0 = qq.x, o0 = oo.x;
    float p1 = pp.y, q1 = qq.y, o1 = oo.y;

#pragma unroll 4
    for (int t = 0; t < CHL; t++) {
        float2 kf = __half22float2(kp[(size_t)t * CD2]);
        float2 vf = __half22float2(vp[(size_t)t * CD2]);

        float uk0 = u0 + kf.x;
        float no0 = fmaxf(o0, uk0);
        float Aa0 = __expf(o0 - no0);
        float Bb0 = __expf(uk0 - no0);
        float y0 = __fdividef(Aa0 * p0 + Bb0 * vf.x, Aa0 * q0 + Bb0);

        float uk1 = u1 + kf.y;
        float no1 = fmaxf(o1, uk1);
        float Aa1 = __expf(o1 - no1);
        float Bb1 = __expf(uk1 - no1);
        float y1 = __fdividef(Aa1 * p1 + Bb1 * vf.y, Aa1 * q1 + Bb1);

        yp[(size_t)t * CD2] = __floats2half2_rn(y0, y1);

        wkv_update(p0, q0, o0, w0, kf.x, vf.x);
        wkv_update(p1, q1, o1, w1, kf.y, vf.y);
    }
}

// ---------------------------------------------------------------------------
// Stage 4: layernorm(y) * sigmoid_r -> z (fp16). Warp per row, 8 rows/block.
// ---------------------------------------------------------------------------
__global__ __launch_bounds__(256)
void ln_gate_kernel(const float* __restrict__ ln_g,
                    const float* __restrict__ ln_b) {
    int wid  = threadIdx.x >> 5;
    int lane = threadIdx.x & 31;
    int row  = blockIdx.x * 8 + wid;
    size_t rbase = (size_t)row * CDIM;
    const uint4* yrow  = (const uint4*)(g_y16  + rbase);
    const uint4* srrow = (const uint4*)(g_sr16 + rbase);

    // 3 x uint4 = 24 halves per lane
    H8 y8[3];
    float yf[24];
    float s = 0.f;
#pragma unroll
    for (int i = 0; i < 3; i++) {
        y8[i].u = yrow[lane + i * 32];
#pragma unroll
        for (int j = 0; j < 4; j++) {
            float2 f2 = __half22float2(y8[i].h2[j]);
            yf[i * 8 + j * 2]     = f2.x;
            yf[i * 8 + j * 2 + 1] = f2.y;
            s += f2.x + f2.y;
        }
    }
#pragma unroll
    for (int off = 16; off > 0; off >>= 1)
        s += __shfl_xor_sync(0xffffffffu, s, off);
    float mu = s * (1.0f / CDIM);

    float ss = 0.f;
#pragma unroll
    for (int i = 0; i < 24; i++) {
        float d = yf[i] - mu;
        ss += d * d;
    }
#pragma unroll
    for (int off = 16; off > 0; off >>= 1)
        ss += __shfl_xor_sync(0xffffffffu, ss, off);
    float rstd = rsqrtf(ss * (1.0f / CDIM) + 1e-5f);

    uint4* zrow = (uint4*)(g_a16[3] + rbase);
#pragma unroll
    for (int i = 0; i < 3; i++) {
        int c0 = (lane + i * 32) * 8;
        H8 sr8; sr8.u = srrow[lane + i * 32];
        H8 zo;
#pragma unroll
        for (int j = 0; j < 4; j++) {
            float2 sr2 = __half22float2(sr8.h2[j]);
            int c = c0 + j * 2;
            float z0 = sr2.x * ((yf[i * 8 + j * 2]     - mu) * rstd * ln_g[c]     + ln_b[c]);
            float z1 = sr2.y * ((yf[i * 8 + j * 2 + 1] - mu) * rstd * ln_g[c + 1] + ln_b[c + 1]);
            zo.h2[j] = __floats2half2_rn(z0, z1);
        }
        zrow[lane + i * 32] = zo.u;
    }
}

// ---------------------------------------------------------------------------
// Launch
// ---------------------------------------------------------------------------
extern "C" void kernel_launch(void* const* d_in, const int* in_sizes, int n_in,
                              void* d_out, int out_size) {
    const float* x   = (const float*)d_in[0];
    const float* sd  = (const float*)d_in[3];
    const float* sf  = (const float*)d_in[4];
    const float* mk  = (const float*)d_in[5];
    const float* mv  = (const float*)d_in[6];
    const float* mr  = (const float*)d_in[7];
    const float* Wk  = (const float*)d_in[8];
    const float* Wv  = (const float*)d_in[9];
    const float* Wr  = (const float*)d_in[10];
    const float* Wo  = (const float*)d_in[11];
    const float* lg  = (const float*)d_in[12];
    const float* lb  = (const float*)d_in[13];
    float* out = (float*)d_out;

    cudaFuncSetAttribute(tc_gemm_kernel,
                         cudaFuncAttributeMaxDynamicSharedMemorySize, SM_GEMM);

    // 0. transpose weights -> fp16
    {
        dim3 blk(32, 8);
        dim3 grd(CDIM / 32, CDIM / 32, 4);
        wtrans_kernel<<<grd, blk>>>(Wk, Wv, Wr, Wo);
    }

    // 1. q_shift + mixes -> fp16
    {
        int n4 = (int)(NELEM / 4);
        shift_mix_kernel<<<(n4 + 255) / 256, 256>>>(x, mk, mv, mr);
    }

    // 2. fused k / v / sr GEMMs (z = 0,1,2)
    {
        dim3 gg(CDIM / 128, MROWS / 128, 3);
        tc_gemm_kernel<<<gg, 256, SM_GEMM>>>(-1, nullptr);
    }

    // 3. WKV chunked scan (fp16 k/v, ILP-2, 32 chunks of 32)
    wkv_p1_kernel<<<(NCH * LANES2) / 256, 256>>>(sd);
    wkv_p2_kernel<<<(LANES + 255) / 256, 256>>>(sd);
    wkv_p3_kernel<<<(NCH * LANES2) / 256, 256>>>(sd, sf);

    // 4. layernorm + gate -> z (fp16)
    ln_gate_kernel<<<MROWS / 8, 256>>>(lg, lb);

    // 5. output projection -> d_out
    {
        dim3 gg(CDIM / 128, MROWS / 128, 1);
        tc_gemm_kernel<<<gg, 256, SM_GEMM>>>(3, out);
    }
}

// round 14
// speedup vs baseline: 1.0616x; 1.0263x over previous
#include <cuda_runtime.h>
#include <cuda_fp16.h>
#include <stdint.h>
#include <math.h>

// Problem constants (fixed by dataset: x is (16, 1024, 768), h=w=32)
#define BDIM 16
#define HDIM 32
#define WDIM 32
#define TDIM (HDIM * WDIM)          // 1024
#define CDIM 768
#define MROWS (BDIM * TDIM)         // 16384
#define QC (CDIM / 4)               // 192

#define NELEM ((size_t)MROWS * CDIM)   // 12,582,912

// WKV chunked-scan config (FROZEN: round-10 optimum)
#define LANES (BDIM * CDIM)         // 12288
#define NCH 32
#define CHL (TDIM / NCH)            // 32

// ---------------------------------------------------------------------------
// Scratch (device globals; no allocation allowed)
// ---------------------------------------------------------------------------
__device__ __half g_a16[4][NELEM];              // 0=xk 1=xv 2=xr 3=z (fp16)
__device__ __half g_wh[4][CDIM * CDIM];         // W^T [N][K] fp16
__device__ __half g_k16[NELEM];
__device__ __half g_v16[NELEM];
__device__ __half g_sr16[NELEM];
__device__ __half g_y16[NELEM];
// wkv chunk-local states and per-chunk initial states
__device__ float g_cp[NCH * LANES], g_cq[NCH * LANES], g_co[NCH * LANES];
__device__ float g_ip[NCH * LANES], g_iq[NCH * LANES], g_io[NCH * LANES];

// ---------------------------------------------------------------------------
// PTX helpers (base sm_103-compatible: mma.sync / ldmatrix / cp.async)
// ---------------------------------------------------------------------------
__device__ __forceinline__ uint32_t smem_u32(const void* p) {
    uint32_t a;
    asm("{ .reg .u64 t; cvta.to.shared.u64 t, %1; cvt.u32.u64 %0, t; }"
        : "=r"(a) : "l"(p));
    return a;
}

__device__ __forceinline__ void ldsm4(uint32_t& r0, uint32_t& r1,
                                      uint32_t& r2, uint32_t& r3, uint32_t addr) {
    asm volatile("ldmatrix.sync.aligned.m8n8.x4.shared.b16 {%0,%1,%2,%3}, [%4];"
                 : "=r"(r0), "=r"(r1), "=r"(r2), "=r"(r3) : "r"(addr));
}

__device__ __forceinline__ void mma16816(float* c, const uint32_t* a, const uint32_t* b) {
    asm volatile(
        "mma.sync.aligned.m16n8k16.row.col.f32.f16.f16.f32 "
        "{%0,%1,%2,%3}, {%4,%5,%6,%7}, {%8,%9}, {%0,%1,%2,%3};"
        : "+f"(c[0]), "+f"(c[1]), "+f"(c[2]), "+f"(c[3])
        : "r"(a[0]), "r"(a[1]), "r"(a[2]), "r"(a[3]), "r"(b[0]), "r"(b[1]));
}

__device__ __forceinline__ void cp16(uint32_t saddr, const void* gptr) {
    asm volatile("cp.async.cg.shared.global [%0], [%1], 16;"
                 :: "r"(saddr), "l"(gptr));
}
#define CP_COMMIT() asm volatile("cp.async.commit_group;" ::: "memory")
#define CP_WAIT2()  asm volatile("cp.async.wait_group 2;" ::: "memory")

// ---------------------------------------------------------------------------
// Stage 0: weight transpose + fp16:  Wt[n][k] = W[k][n]
// ---------------------------------------------------------------------------
__global__ void wtrans_kernel(const float* __restrict__ W0, const float* __restrict__ W1,
                              const float* __restrict__ W2, const float* __restrict__ W3) {
    __shared__ float s[32][33];
    const float* W = (blockIdx.z == 0) ? W0 : (blockIdx.z == 1) ? W1
                   : (blockIdx.z == 2) ? W2 : W3;
    int n0 = blockIdx.x * 32, k0 = blockIdx.y * 32;
    int tx = threadIdx.x, ty = threadIdx.y;   // 32 x 8
#pragma unroll
    for (int i = 0; i < 4; i++) {
        int kk = ty + i * 8;
        s[kk][tx] = W[(size_t)(k0 + kk) * CDIM + n0 + tx];
    }
    __syncthreads();
#pragma unroll
    for (int i = 0; i < 4; i++) {
        int nn = ty + i * 8;
        float v = s[tx][nn];                  // = W[k0+tx][n0+nn]
        g_wh[blockIdx.z][(size_t)(n0 + nn) * CDIM + k0 + tx] = __float2half(v);
    }
}

// ---------------------------------------------------------------------------
// Stage 1: q_shift + token mixes -> fp16 (xk, xv, xr), 8 channels/thread
// ---------------------------------------------------------------------------
union H4 { __half h[4]; __half2 h2[2]; uint2 u; };
union H8 { __half h[8]; __half2 h2[4]; uint4 u; };

__device__ __forceinline__ void store_h8(int sel, size_t base,
                                         const float* v) {
    H8 o;
#pragma unroll
    for (int j = 0; j < 4; j++)
        o.h2[j] = __floats2half2_rn(v[j * 2], v[j * 2 + 1]);
    *(uint4*)(&g_a16[sel][base]) = o.u;
}

__global__ void shift_mix_kernel(const float* __restrict__ x,
                                 const float* __restrict__ mix_k,
                                 const float* __restrict__ mix_v,
                                 const float* __restrict__ mix_r) {
    int idx8 = blockIdx.x * blockDim.x + threadIdx.x;
    if (idx8 >= (int)(NELEM / 8)) return;
    int cq = idx8 % (CDIM / 8);
    int sp = idx8 / (CDIM / 8);
    int c  = cq * 8;
    size_t base = (size_t)sp * CDIM + c;
    int wq = sp % WDIM;
    int hq = (sp / WDIM) % HDIM;

    float xx[8] = {0.f, 0.f, 0.f, 0.f, 0.f, 0.f, 0.f, 0.f};
    int g = c / QC;                           // QC=192 divisible by 8
    long long soff = 0; bool have = false;
    if (g == 0)       { have = (wq > 0);        soff = -(long long)CDIM; }
    else if (g == 1)  { have = (wq < WDIM - 1); soff =  (long long)CDIM; }
    else if (g == 2)  { have = (hq > 0);        soff = -(long long)WDIM * CDIM; }
    else              { have = (hq < HDIM - 1); soff =  (long long)WDIM * CDIM; }
    if (have) {
        float4 a = *(const float4*)(x + base + soff);
        float4 b = *(const float4*)(x + base + soff + 4);
        xx[0] = a.x; xx[1] = a.y; xx[2] = a.z; xx[3] = a.w;
        xx[4] = b.x; xx[5] = b.y; xx[6] = b.z; xx[7] = b.w;
    }

    float xc[8], mk[8], mv[8], mr[8];
    {
        float4 a = *(const float4*)(x + base);
        float4 b = *(const float4*)(x + base + 4);
        xc[0] = a.x; xc[1] = a.y; xc[2] = a.z; xc[3] = a.w;
        xc[4] = b.x; xc[5] = b.y; xc[6] = b.z; xc[7] = b.w;
        float4 p = *(const float4*)(mix_k + c);
        float4 q = *(const float4*)(mix_k + c + 4);
        mk[0] = p.x; mk[1] = p.y; mk[2] = p.z; mk[3] = p.w;
        mk[4] = q.x; mk[5] = q.y; mk[6] = q.z; mk[7] = q.w;
        p = *(const float4*)(mix_v + c);
        q = *(const float4*)(mix_v + c + 4);
        mv[0] = p.x; mv[1] = p.y; mv[2] = p.z; mv[3] = p.w;
        mv[4] = q.x; mv[5] = q.y; mv[6] = q.z; mv[7] = q.w;
        p = *(const float4*)(mix_r + c);
        q = *(const float4*)(mix_r + c + 4);
        mr[0] = p.x; mr[1] = p.y; mr[2] = p.z; mr[3] = p.w;
        mr[4] = q.x; mr[5] = q.y; mr[6] = q.z; mr[7] = q.w;
    }

    float vk[8], vv[8], vr[8];
#pragma unroll
    for (int j = 0; j < 8; j++) {
        vk[j] = xc[j] * mk[j] + xx[j] * (1.f - mk[j]);
        vv[j] = xc[j] * mv[j] + xx[j] * (1.f - mv[j]);
        vr[j] = xc[j] * mr[j] + xx[j] * (1.f - mr[j]);
    }
    store_h8(0, base, vk);
    store_h8(1, base, vv);
    store_h8(2, base, vr);
}

// ---------------------------------------------------------------------------
// Stage 2/5: fp16 tensor-core GEMM via mma.sync (single pass).
// (FROZEN configuration — round-7 optimum.)
// ---------------------------------------------------------------------------
#define TILEB 8192                         // 128 rows * 64B
#define STAGEB (2 * TILEB)                 // 16384: [A | Wh]
#define NSTAGE 4
#define SM_GEMM (NSTAGE * STAGEB)          // 65536

__device__ __forceinline__ uint32_t swz_off(int row, int cc) {
    return (uint32_t)(row * 64 + ((cc ^ ((row >> 1) & 3)) << 4));
}

__global__ __launch_bounds__(256, 2)
void tc_gemm_kernel(int aSel, float* __restrict__ cOut) {
    extern __shared__ char smem[];
    const uint32_t sb = smem_u32(smem);
    const int tid = threadIdx.x;
    const int w = tid >> 5, l = tid & 31;
    const int wm = w >> 2, wn = w & 3;

    const int s = (aSel < 0) ? (int)blockIdx.z : aSel;

    const __half* __restrict__ A  = g_a16[s];
    const __half* __restrict__ Wh = g_wh[s];

    const int mrow0 = blockIdx.y * 128;
    const int ncol0 = blockIdx.x * 128;

    float acc[4][4][4];
#pragma unroll
    for (int i = 0; i < 4; i++)
#pragma unroll
        for (int j = 0; j < 4; j++)
#pragma unroll
            for (int q = 0; q < 4; q++) acc[i][j][q] = 0.0f;

    auto issue = [&](int kc, int st) {
        if (kc < 24) {
            uint32_t s0 = sb + st * STAGEB;
#pragma unroll
            for (int j = 0; j < 2; j++) {
                int id = tid + j * 256;          // 0..511
                int row = id >> 2, cc = id & 3;
                size_t gA = (size_t)(mrow0 + row) * CDIM + kc * 32 + cc * 8;
                size_t gB = (size_t)(ncol0 + row) * CDIM + kc * 32 + cc * 8;
                uint32_t so = swz_off(row, cc);
                cp16(s0 + 0 * TILEB + so, A  + gA);
                cp16(s0 + 1 * TILEB + so, Wh + gB);
            }
        }
        CP_COMMIT();
    };

    issue(0, 0); issue(1, 1); issue(2, 2);

    const int aRow = wm * 64 + (l & 15);
    const int aC0  = l >> 4;                    // 0..1
    const int aSwz = (aRow >> 1) & 3;
    const int bRow = wn * 32 + ((l & 7) | ((l >> 4) << 3));
    const int bC0  = (l >> 3) & 1;
    const int bSwz = (bRow >> 1) & 3;

    for (int kc = 0; kc < 24; kc++) {
        int st = kc & 3;
        CP_WAIT2();
        __syncthreads();
        issue(kc + 3, (kc + 3) & 3);
        uint32_t s0 = sb + st * STAGEB;
#pragma unroll
        for (int ks = 0; ks < 2; ks++) {
            uint32_t a[4][4], bh[2][4];
            uint32_t aA = s0 + aRow * 64 + (((aC0 + ks * 2) ^ aSwz) << 4);
            uint32_t bA = s0 + TILEB + bRow * 64 + (((bC0 + ks * 2) ^ bSwz) << 4);
#pragma unroll
            for (int am = 0; am < 4; am++)
                ldsm4(a[am][0], a[am][1], a[am][2], a[am][3],
                      aA + am * 1024);                       // +16 rows
#pragma unroll
            for (int bn = 0; bn < 2; bn++)
                ldsm4(bh[bn][0], bh[bn][1], bh[bn][2], bh[bn][3],
                      bA + bn * 1024);
#pragma unroll
            for (int am = 0; am < 4; am++)
#pragma unroll
                for (int an = 0; an < 4; an++)
                    mma16816(acc[am][an], a[am], &bh[an >> 1][(an & 1) * 2]);
        }
    }

    // Epilogue. s==0/1/2 -> fp16 k/v/sr (sigmoid for s==2); s==3 -> fp32 out.
    if (s <= 2) {
        __half* __restrict__ Ch = (s == 0) ? g_k16 : (s == 1) ? g_v16 : g_sr16;
        const bool sig = (s == 2);
#pragma unroll
        for (int am = 0; am < 4; am++) {
            int r0 = mrow0 + wm * 64 + am * 16 + (l >> 2);
#pragma unroll
            for (int an = 0; an < 4; an++) {
                int cc = ncol0 + wn * 32 + an * 8 + (l & 3) * 2;
                float v0 = acc[am][an][0], v1 = acc[am][an][1];
                float v2 = acc[am][an][2], v3 = acc[am][an][3];
                if (sig) {
                    v0 = 1.0f / (1.0f + __expf(-v0));
                    v1 = 1.0f / (1.0f + __expf(-v1));
                    v2 = 1.0f / (1.0f + __expf(-v2));
                    v3 = 1.0f / (1.0f + __expf(-v3));
                }
                *(__half2*)(Ch + (size_t)r0 * CDIM + cc) =
                    __floats2half2_rn(v0, v1);
                *(__half2*)(Ch + (size_t)(r0 + 8) * CDIM + cc) =
                    __floats2half2_rn(v2, v3);
            }
        }
    } else {
#pragma unroll
        for (int am = 0; am < 4; am++) {
            int r0 = mrow0 + wm * 64 + am * 16 + (l >> 2);
#pragma unroll
            for (int an = 0; an < 4; an++) {
                int cc = ncol0 + wn * 32 + an * 8 + (l & 3) * 2;
                *(float2*)(cOut + (size_t)r0 * CDIM + cc) =
                    make_float2(acc[am][an][0], acc[am][an][1]);
                *(float2*)(cOut + (size_t)(r0 + 8) * CDIM + cc) =
                    make_float2(acc[am][an][2], acc[am][an][3]);
            }
        }
    }
}

// ---------------------------------------------------------------------------
// Stage 3: WKV 3-phase chunked scan, fp16 k/v, ILP-2.
// p1/p3 run in fixed-base (unnormalized) space: within a 32-step chunk the
// exponents are bounded (|k| <~ 5), so no per-step max-rescale is needed.
// ---------------------------------------------------------------------------
#define CD2 (CDIM / 2)
#define LANES2 (LANES / 2)

__global__ void wkv_p1_kernel(const float* __restrict__ spatial_decay) {
    int idx = blockIdx.x * blockDim.x + threadIdx.x;   // 0..NCH*LANES2-1
    if (idx >= NCH * LANES2) return;
    int chunk = idx / LANES2;
    int l2    = idx % LANES2;
    int c2 = l2 % CD2, b = l2 / CD2;
    int c = c2 * 2;
    const float inv_t = 1.0f / (float)TDIM;
    float ew0 = __expf(spatial_decay[c]     * inv_t);
    float ew1 = __expf(spatial_decay[c + 1] * inv_t);

    const __half2* kp = (const __half2*)(g_k16 + ((size_t)b * TDIM + chunk * CHL) * CDIM) + c2;
    const __half2* vp = (const __half2*)(g_v16 + ((size_t)b * TDIM + chunk * CHL) * CDIM) + c2;

    // unnormalized chunk-local state (o == 0)
    float p0 = 0.f, q0 = 0.f;
    float p1 = 0.f, q1 = 0.f;
#pragma unroll 4
    for (int t = 0; t < CHL; t++) {
        float2 kf = __half22float2(kp[(size_t)t * CD2]);
        float2 vf = __half22float2(vp[(size_t)t * CD2]);
        float e0 = __expf(kf.x);
        float e1 = __expf(kf.y);
        p0 = fmaf(ew0, p0, vf.x * e0);
        q0 = fmaf(ew0, q0, e0);
        p1 = fmaf(ew1, p1, vf.y * e1);
        q1 = fmaf(ew1, q1, e1);
    }

    int i0 = chunk * LANES + b * CDIM + c;
    *(float2*)(g_cp + i0) = make_float2(p0, p1);
    *(float2*)(g_cq + i0) = make_float2(q0, q1);
    *(float2*)(g_co + i0) = make_float2(0.f, 0.f);
}

__global__ void wkv_p2_kernel(const float* __restrict__ spatial_decay) {
    int lane = blockIdx.x * blockDim.x + threadIdx.x;
    if (lane >= LANES) return;
    int c = lane % CDIM;
    float wL = spatial_decay[c] * (1.0f / (float)TDIM) * (float)CHL;

    float p = 0.f, q = 0.f, o = -1e38f;
#pragma unroll
    for (int j = 0; j < NCH; j++) {
        int idx = j * LANES + lane;
        g_ip[idx] = p; g_iq[idx] = q; g_io[idx] = o;
        float cp = g_cp[idx], cq = g_cq[idx], co = g_co[idx];
        float ow = o + wL;
        float no = fmaxf(ow, co);
        float A = __expf(ow - no);
        float B = __expf(co - no);
        p = A * p + B * cp;
        q = A * q + B * cq;
        o = no;
    }
}

__global__ void wkv_p3_kernel(const float* __restrict__ spatial_decay,
                              const float* __restrict__ spatial_first) {
    int idx = blockIdx.x * blockDim.x + threadIdx.x;
    if (idx >= NCH * LANES2) return;
    int chunk = idx / LANES2;
    int l2    = idx % LANES2;
    int c2 = l2 % CD2, b = l2 / CD2;
    int c = c2 * 2;
    const float inv_t = 1.0f / (float)TDIM;
    float ew0 = __expf(spatial_decay[c]     * inv_t);
    float ew1 = __expf(spatial_decay[c + 1] * inv_t);
    float eu0 = __expf(spatial_first[c]     * inv_t);
    float eu1 = __expf(spatial_first[c + 1] * inv_t);

    const __half2* kp = (const __half2*)(g_k16 + ((size_t)b * TDIM + chunk * CHL) * CDIM) + c2;
    const __half2* vp = (const __half2*)(g_v16 + ((size_t)b * TDIM + chunk * CHL) * CDIM) + c2;
    __half2*       yp = (__half2*)(g_y16 + ((size_t)b * TDIM + chunk * CHL) * CDIM) + c2;

    int i0 = chunk * LANES + b * CDIM + c;
    float2 pp = *(const float2*)(g_ip + i0);
    float2 qq = *(const float2*)(g_iq + i0);
    float2 oo = *(const float2*)(g_io + i0);
    // fixed exponent base for the whole chunk; clamp is exact when p=q=0
    float oi0 = fmaxf(oo.x, -30.f);
    float oi1 = fmaxf(oo.y, -30.f);
    float P0 = pp.x, Q0 = qq.x;
    float P1 = pp.y, Q1 = qq.y;

#pragma unroll 4
    for (int t = 0; t < CHL; t++) {
        float2 kf = __half22float2(kp[(size_t)t * CD2]);
        float2 vf = __half22float2(vp[(size_t)t * CD2]);

        float ek0 = __expf(kf.x - oi0);
        float ek1 = __expf(kf.y - oi1);
        float E0 = ek0 * eu0;
        float E1 = ek1 * eu1;
        float y0 = __fdividef(fmaf(E0, vf.x, P0), Q0 + E0);
        float y1 = __fdividef(fmaf(E1, vf.y, P1), Q1 + E1);
        yp[(size_t)t * CD2] = __floats2half2_rn(y0, y1);

        P0 = fmaf(ew0, P0, vf.x * ek0);
        Q0 = fmaf(ew0, Q0, ek0);
        P1 = fmaf(ew1, P1, vf.y * ek1);
        Q1 = fmaf(ew1, Q1, ek1);
    }
}

// ---------------------------------------------------------------------------
// Stage 4: layernorm(y) * sigmoid_r -> z (fp16). Warp per row, 8 rows/block.
// ---------------------------------------------------------------------------
__global__ __launch_bounds__(256)
void ln_gate_kernel(const float* __restrict__ ln_g,
                    const float* __restrict__ ln_b) {
    int wid  = threadIdx.x >> 5;
    int lane = threadIdx.x & 31;
    int row  = blockIdx.x * 8 + wid;
    size_t rbase = (size_t)row * CDIM;
    const uint4* yrow  = (const uint4*)(g_y16  + rbase);
    const uint4* srrow = (const uint4*)(g_sr16 + rbase);

    // 3 x uint4 = 24 halves per lane
    H8 y8[3];
    float yf[24];
    float s = 0.f;
#pragma unroll
    for (int i = 0; i < 3; i++) {
        y8[i].u = yrow[lane + i * 32];
#pragma unroll
        for (int j = 0; j < 4; j++) {
            float2 f2 = __half22float2(y8[i].h2[j]);
            yf[i * 8 + j * 2]     = f2.x;
            yf[i * 8 + j * 2 + 1] = f2.y;
            s += f2.x + f2.y;
        }
    }
#pragma unroll
    for (int off = 16; off > 0; off >>= 1)
        s += __shfl_xor_sync(0xffffffffu, s, off);
    float mu = s * (1.0f / CDIM);

    float ss = 0.f;
#pragma unroll
    for (int i = 0; i < 24; i++) {
        float d = yf[i] - mu;
        ss += d * d;
    }
#pragma unroll
    for (int off = 16; off > 0; off >>= 1)
        ss += __shfl_xor_sync(0xffffffffu, ss, off);
    float rstd = rsqrtf(ss * (1.0f / CDIM) + 1e-5f);

    uint4* zrow = (uint4*)(g_a16[3] + rbase);
#pragma unroll
    for (int i = 0; i < 3; i++) {
        int c0 = (lane + i * 32) * 8;
        H8 sr8; sr8.u = srrow[lane + i * 32];
        H8 zo;
#pragma unroll
        for (int j = 0; j < 4; j++) {
            float2 sr2 = __half22float2(sr8.h2[j]);
            int c = c0 + j * 2;
            float z0 = sr2.x * ((yf[i * 8 + j * 2]     - mu) * rstd * ln_g[c]     + ln_b[c]);
            float z1 = sr2.y * ((yf[i * 8 + j * 2 + 1] - mu) * rstd * ln_g[c + 1] + ln_b[c + 1]);
            zo.h2[j] = __floats2half2_rn(z0, z1);
        }
        zrow[lane + i * 32] = zo.u;
    }
}

// ---------------------------------------------------------------------------
// Launch
// ---------------------------------------------------------------------------
extern "C" void kernel_launch(void* const* d_in, const int* in_sizes, int n_in,
                              void* d_out, int out_size) {
    const float* x   = (const float*)d_in[0];
    const float* sd  = (const float*)d_in[3];
    const float* sf  = (const float*)d_in[4];
    const float* mk  = (const float*)d_in[5];
    const float* mv  = (const float*)d_in[6];
    const float* mr  = (const float*)d_in[7];
    const float* Wk  = (const float*)d_in[8];
    const float* Wv  = (const float*)d_in[9];
    const float* Wr  = (const float*)d_in[10];
    const float* Wo  = (const float*)d_in[11];
    const float* lg  = (const float*)d_in[12];
    const float* lb  = (const float*)d_in[13];
    float* out = (float*)d_out;

    cudaFuncSetAttribute(tc_gemm_kernel,
                         cudaFuncAttributeMaxDynamicSharedMemorySize, SM_GEMM);

    // 0. transpose weights -> fp16
    {
        dim3 blk(32, 8);
        dim3 grd(CDIM / 32, CDIM / 32, 4);
        wtrans_kernel<<<grd, blk>>>(Wk, Wv, Wr, Wo);
    }

    // 1. q_shift + mixes -> fp16 (8 channels/thread)
    {
        int n8 = (int)(NELEM / 8);
        shift_mix_kernel<<<(n8 + 255) / 256, 256>>>(x, mk, mv, mr);
    }

    // 2. fused k / v / sr GEMMs (z = 0,1,2)
    {
        dim3 gg(CDIM / 128, MROWS / 128, 3);
        tc_gemm_kernel<<<gg, 256, SM_GEMM>>>(-1, nullptr);
    }

    // 3. WKV chunked scan (fp16 k/v, ILP-2, fixed-base exponents)
    wkv_p1_kernel<<<(NCH * LANES2) / 256, 256>>>(sd);
    wkv_p2_kernel<<<(LANES + 255) / 256, 256>>>(sd);
    wkv_p3_kernel<<<(NCH * LANES2) / 256, 256>>>(sd, sf);

    // 4. layernorm + gate -> z (fp16)
    ln_gate_kernel<<<MROWS / 8, 256>>>(lg, lb);

    // 5. output projection -> d_out
    {
        dim3 gg(CDIM / 128, MROWS / 128, 1);
        tc_gemm_kernel<<<gg, 256, SM_GEMM>>>(3, out);
    }
}

// round 15
// speedup vs baseline: 1.0624x; 1.0008x over previous
#include <cuda_runtime.h>
#include <cuda_fp16.h>
#include <stdint.h>
#include <math.h>

// Problem constants (fixed by dataset: x is (16, 1024, 768), h=w=32)
#define BDIM 16
#define HDIM 32
#define WDIM 32
#define TDIM (HDIM * WDIM)          // 1024
#define CDIM 768
#define MROWS (BDIM * TDIM)         // 16384
#define QC (CDIM / 4)               // 192

#define NELEM ((size_t)MROWS * CDIM)   // 12,582,912

// WKV chunked-scan config (FROZEN: round-10 optimum)
#define LANES (BDIM * CDIM)         // 12288
#define NCH 32
#define CHL (TDIM / NCH)            // 32

// ---------------------------------------------------------------------------
// Scratch (device globals; no allocation allowed)
// ---------------------------------------------------------------------------
__device__ __half g_a16[4][NELEM];              // 0=xk 1=xv 2=xr 3=z (fp16)
__device__ __half g_wh[4][CDIM * CDIM];         // W^T [N][K] fp16
__device__ __half g_k16[NELEM];
__device__ __half g_v16[NELEM];
__device__ __half g_sr16[NELEM];
__device__ __half g_y16[NELEM];
// wkv chunk-local states and per-chunk initial states
__device__ float g_cp[NCH * LANES], g_cq[NCH * LANES], g_co[NCH * LANES];
__device__ float g_ip[NCH * LANES], g_iq[NCH * LANES], g_io[NCH * LANES];

// ---------------------------------------------------------------------------
// PTX helpers (base sm_103-compatible: mma.sync / ldmatrix / cp.async)
// ---------------------------------------------------------------------------
__device__ __forceinline__ uint32_t smem_u32(const void* p) {
    uint32_t a;
    asm("{ .reg .u64 t; cvta.to.shared.u64 t, %1; cvt.u32.u64 %0, t; }"
        : "=r"(a) : "l"(p));
    return a;
}

__device__ __forceinline__ void ldsm4(uint32_t& r0, uint32_t& r1,
                                      uint32_t& r2, uint32_t& r3, uint32_t addr) {
    asm volatile("ldmatrix.sync.aligned.m8n8.x4.shared.b16 {%0,%1,%2,%3}, [%4];"
                 : "=r"(r0), "=r"(r1), "=r"(r2), "=r"(r3) : "r"(addr));
}

__device__ __forceinline__ void mma16816(float* c, const uint32_t* a, const uint32_t* b) {
    asm volatile(
        "mma.sync.aligned.m16n8k16.row.col.f32.f16.f16.f32 "
        "{%0,%1,%2,%3}, {%4,%5,%6,%7}, {%8,%9}, {%0,%1,%2,%3};"
        : "+f"(c[0]), "+f"(c[1]), "+f"(c[2]), "+f"(c[3])
        : "r"(a[0]), "r"(a[1]), "r"(a[2]), "r"(a[3]), "r"(b[0]), "r"(b[1]));
}

__device__ __forceinline__ void cp16(uint32_t saddr, const void* gptr) {
    asm volatile("cp.async.cg.shared.global [%0], [%1], 16;"
                 :: "r"(saddr), "l"(gptr));
}
#define CP_COMMIT() asm volatile("cp.async.commit_group;" ::: "memory")
#define CP_WAIT2()  asm volatile("cp.async.wait_group 2;" ::: "memory")

// ---------------------------------------------------------------------------
// Stage 0: weight transpose + fp16:  Wt[n][k] = W[k][n]
// ---------------------------------------------------------------------------
__global__ void wtrans_kernel(const float* __restrict__ W0, const float* __restrict__ W1,
                              const float* __restrict__ W2, const float* __restrict__ W3) {
    __shared__ float s[32][33];
    const float* W = (blockIdx.z == 0) ? W0 : (blockIdx.z == 1) ? W1
                   : (blockIdx.z == 2) ? W2 : W3;
    int n0 = blockIdx.x * 32, k0 = blockIdx.y * 32;
    int tx = threadIdx.x, ty = threadIdx.y;   // 32 x 8
#pragma unroll
    for (int i = 0; i < 4; i++) {
        int kk = ty + i * 8;
        s[kk][tx] = W[(size_t)(k0 + kk) * CDIM + n0 + tx];
    }
    __syncthreads();
#pragma unroll
    for (int i = 0; i < 4; i++) {
        int nn = ty + i * 8;
        float v = s[tx][nn];                  // = W[k0+tx][n0+nn]
        g_wh[blockIdx.z][(size_t)(n0 + nn) * CDIM + k0 + tx] = __float2half(v);
    }
}

// ---------------------------------------------------------------------------
// Stage 1: q_shift + token mixes -> fp16 (xk, xv, xr), 8 channels/thread
// ---------------------------------------------------------------------------
union H4 { __half h[4]; __half2 h2[2]; uint2 u; };
union H8 { __half h[8]; __half2 h2[4]; uint4 u; };

__device__ __forceinline__ void store_h8(int sel, size_t base,
                                         const float* v) {
    H8 o;
#pragma unroll
    for (int j = 0; j < 4; j++)
        o.h2[j] = __floats2half2_rn(v[j * 2], v[j * 2 + 1]);
    *(uint4*)(&g_a16[sel][base]) = o.u;
}

__global__ void shift_mix_kernel(const float* __restrict__ x,
                                 const float* __restrict__ mix_k,
                                 const float* __restrict__ mix_v,
                                 const float* __restrict__ mix_r) {
    int idx8 = blockIdx.x * blockDim.x + threadIdx.x;
    if (idx8 >= (int)(NELEM / 8)) return;
    int cq = idx8 % (CDIM / 8);
    int sp = idx8 / (CDIM / 8);
    int c  = cq * 8;
    size_t base = (size_t)sp * CDIM + c;
    int wq = sp % WDIM;
    int hq = (sp / WDIM) % HDIM;

    float xx[8] = {0.f, 0.f, 0.f, 0.f, 0.f, 0.f, 0.f, 0.f};
    int g = c / QC;                           // QC=192 divisible by 8
    long long soff = 0; bool have = false;
    if (g == 0)       { have = (wq > 0);        soff = -(long long)CDIM; }
    else if (g == 1)  { have = (wq < WDIM - 1); soff =  (long long)CDIM; }
    else if (g == 2)  { have = (hq > 0);        soff = -(long long)WDIM * CDIM; }
    else              { have = (hq < HDIM - 1); soff =  (long long)WDIM * CDIM; }
    if (have) {
        float4 a = *(const float4*)(x + base + soff);
        float4 b = *(const float4*)(x + base + soff + 4);
        xx[0] = a.x; xx[1] = a.y; xx[2] = a.z; xx[3] = a.w;
        xx[4] = b.x; xx[5] = b.y; xx[6] = b.z; xx[7] = b.w;
    }

    float xc[8], mk[8], mv[8], mr[8];
    {
        float4 a = *(const float4*)(x + base);
        float4 b = *(const float4*)(x + base + 4);
        xc[0] = a.x; xc[1] = a.y; xc[2] = a.z; xc[3] = a.w;
        xc[4] = b.x; xc[5] = b.y; xc[6] = b.z; xc[7] = b.w;
        float4 p = *(const float4*)(mix_k + c);
        float4 q = *(const float4*)(mix_k + c + 4);
        mk[0] = p.x; mk[1] = p.y; mk[2] = p.z; mk[3] = p.w;
        mk[4] = q.x; mk[5] = q.y; mk[6] = q.z; mk[7] = q.w;
        p = *(const float4*)(mix_v + c);
        q = *(const float4*)(mix_v + c + 4);
        mv[0] = p.x; mv[1] = p.y; mv[2] = p.z; mv[3] = p.w;
        mv[4] = q.x; mv[5] = q.y; mv[6] = q.z; mv[7] = q.w;
        p = *(const float4*)(mix_r + c);
        q = *(const float4*)(mix_r + c + 4);
        mr[0] = p.x; mr[1] = p.y; mr[2] = p.z; mr[3] = p.w;
        mr[4] = q.x; mr[5] = q.y; mr[6] = q.z; mr[7] = q.w;
    }

    float vk[8], vv[8], vr[8];
#pragma unroll
    for (int j = 0; j < 8; j++) {
        vk[j] = xc[j] * mk[j] + xx[j] * (1.f - mk[j]);
        vv[j] = xc[j] * mv[j] + xx[j] * (1.f - mv[j]);
        vr[j] = xc[j] * mr[j] + xx[j] * (1.f - mr[j]);
    }
    store_h8(0, base, vk);
    store_h8(1, base, vv);
    store_h8(2, base, vr);
}

// ---------------------------------------------------------------------------
// Stage 2/5: fp16 tensor-core GEMM via mma.sync (single pass).
// (FROZEN configuration — round-7 optimum.)
// ---------------------------------------------------------------------------
#define TILEB 8192                         // 128 rows * 64B
#define STAGEB (2 * TILEB)                 // 16384: [A | Wh]
#define NSTAGE 4
#define SM_GEMM (NSTAGE * STAGEB)          // 65536

__device__ __forceinline__ uint32_t swz_off(int row, int cc) {
    return (uint32_t)(row * 64 + ((cc ^ ((row >> 1) & 3)) << 4));
}

__global__ __launch_bounds__(256, 2)
void tc_gemm_kernel(int aSel, float* __restrict__ cOut) {
    extern __shared__ char smem[];
    const uint32_t sb = smem_u32(smem);
    const int tid = threadIdx.x;
    const int w = tid >> 5, l = tid & 31;
    const int wm = w >> 2, wn = w & 3;

    const int s = (aSel < 0) ? (int)blockIdx.z : aSel;

    const __half* __restrict__ A  = g_a16[s];
    const __half* __restrict__ Wh = g_wh[s];

    const int mrow0 = blockIdx.y * 128;
    const int ncol0 = blockIdx.x * 128;

    float acc[4][4][4];
#pragma unroll
    for (int i = 0; i < 4; i++)
#pragma unroll
        for (int j = 0; j < 4; j++)
#pragma unroll
            for (int q = 0; q < 4; q++) acc[i][j][q] = 0.0f;

    auto issue = [&](int kc, int st) {
        if (kc < 24) {
            uint32_t s0 = sb + st * STAGEB;
#pragma unroll
            for (int j = 0; j < 2; j++) {
                int id = tid + j * 256;          // 0..511
                int row = id >> 2, cc = id & 3;
                size_t gA = (size_t)(mrow0 + row) * CDIM + kc * 32 + cc * 8;
                size_t gB = (size_t)(ncol0 + row) * CDIM + kc * 32 + cc * 8;
                uint32_t so = swz_off(row, cc);
                cp16(s0 + 0 * TILEB + so, A  + gA);
                cp16(s0 + 1 * TILEB + so, Wh + gB);
            }
        }
        CP_COMMIT();
    };

    issue(0, 0); issue(1, 1); issue(2, 2);

    const int aRow = wm * 64 + (l & 15);
    const int aC0  = l >> 4;                    // 0..1
    const int aSwz = (aRow >> 1) & 3;
    const int bRow = wn * 32 + ((l & 7) | ((l >> 4) << 3));
    const int bC0  = (l >> 3) & 1;
    const int bSwz = (bRow >> 1) & 3;

    for (int kc = 0; kc < 24; kc++) {
        int st = kc & 3;
        CP_WAIT2();
        __syncthreads();
        issue(kc + 3, (kc + 3) & 3);
        uint32_t s0 = sb + st * STAGEB;
#pragma unroll
        for (int ks = 0; ks < 2; ks++) {
            uint32_t a[4][4], bh[2][4];
            uint32_t aA = s0 + aRow * 64 + (((aC0 + ks * 2) ^ aSwz) << 4);
            uint32_t bA = s0 + TILEB + bRow * 64 + (((bC0 + ks * 2) ^ bSwz) << 4);
#pragma unroll
            for (int am = 0; am < 4; am++)
                ldsm4(a[am][0], a[am][1], a[am][2], a[am][3],
                      aA + am * 1024);                       // +16 rows
#pragma unroll
            for (int bn = 0; bn < 2; bn++)
                ldsm4(bh[bn][0], bh[bn][1], bh[bn][2], bh[bn][3],
                      bA + bn * 1024);
#pragma unroll
            for (int am = 0; am < 4; am++)
#pragma unroll
                for (int an = 0; an < 4; an++)
                    mma16816(acc[am][an], a[am], &bh[an >> 1][(an & 1) * 2]);
        }
    }

    // Epilogue. s==0/1/2 -> fp16 k/v/sr (sigmoid for s==2); s==3 -> fp32 out.
    if (s <= 2) {
        __half* __restrict__ Ch = (s == 0) ? g_k16 : (s == 1) ? g_v16 : g_sr16;
        const bool sig = (s == 2);
#pragma unroll
        for (int am = 0; am < 4; am++) {
            int r0 = mrow0 + wm * 64 + am * 16 + (l >> 2);
#pragma unroll
            for (int an = 0; an < 4; an++) {
                int cc = ncol0 + wn * 32 + an * 8 + (l & 3) * 2;
                float v0 = acc[am][an][0], v1 = acc[am][an][1];
                float v2 = acc[am][an][2], v3 = acc[am][an][3];
                if (sig) {
                    v0 = 1.0f / (1.0f + __expf(-v0));
                    v1 = 1.0f / (1.0f + __expf(-v1));
                    v2 = 1.0f / (1.0f + __expf(-v2));
                    v3 = 1.0f / (1.0f + __expf(-v3));
                }
                *(__half2*)(Ch + (size_t)r0 * CDIM + cc) =
                    __floats2half2_rn(v0, v1);
                *(__half2*)(Ch + (size_t)(r0 + 8) * CDIM + cc) =
                    __floats2half2_rn(v2, v3);
            }
        }
    } else {
#pragma unroll
        for (int am = 0; am < 4; am++) {
            int r0 = mrow0 + wm * 64 + am * 16 + (l >> 2);
#pragma unroll
            for (int an = 0; an < 4; an++) {
                int cc = ncol0 + wn * 32 + an * 8 + (l & 3) * 2;
                *(float2*)(cOut + (size_t)r0 * CDIM + cc) =
                    make_float2(acc[am][an][0], acc[am][an][1]);
                *(float2*)(cOut + (size_t)(r0 + 8) * CDIM + cc) =
                    make_float2(acc[am][an][2], acc[am][an][3]);
            }
        }
    }
}

// ---------------------------------------------------------------------------
// Stage 3: WKV 3-phase chunked scan, fp16 k/v, ILP-2, fixed-base exponents.
// ---------------------------------------------------------------------------
#define CD2 (CDIM / 2)
#define LANES2 (LANES / 2)

__global__ void wkv_p1_kernel(const float* __restrict__ spatial_decay) {
    int idx = blockIdx.x * blockDim.x + threadIdx.x;   // 0..NCH*LANES2-1
    if (idx >= NCH * LANES2) return;
    int chunk = idx / LANES2;
    int l2    = idx % LANES2;
    int c2 = l2 % CD2, b = l2 / CD2;
    int c = c2 * 2;
    const float inv_t = 1.0f / (float)TDIM;
    float ew0 = __expf(spatial_decay[c]     * inv_t);
    float ew1 = __expf(spatial_decay[c + 1] * inv_t);

    const __half2* kp = (const __half2*)(g_k16 + ((size_t)b * TDIM + chunk * CHL) * CDIM) + c2;
    const __half2* vp = (const __half2*)(g_v16 + ((size_t)b * TDIM + chunk * CHL) * CDIM) + c2;

    // unnormalized chunk-local state (o == 0)
    float p0 = 0.f, q0 = 0.f;
    float p1 = 0.f, q1 = 0.f;
#pragma unroll 4
    for (int t = 0; t < CHL; t++) {
        float2 kf = __half22float2(kp[(size_t)t * CD2]);
        float2 vf = __half22float2(vp[(size_t)t * CD2]);
        float e0 = __expf(kf.x);
        float e1 = __expf(kf.y);
        p0 = fmaf(ew0, p0, vf.x * e0);
        q0 = fmaf(ew0, q0, e0);
        p1 = fmaf(ew1, p1, vf.y * e1);
        q1 = fmaf(ew1, q1, e1);
    }

    int i0 = chunk * LANES + b * CDIM + c;
    *(float2*)(g_cp + i0) = make_float2(p0, p1);
    *(float2*)(g_cq + i0) = make_float2(q0, q1);
    *(float2*)(g_co + i0) = make_float2(0.f, 0.f);
}

__global__ void wkv_p2_kernel(const float* __restrict__ spatial_decay) {
    int lane = blockIdx.x * blockDim.x + threadIdx.x;
    if (lane >= LANES) return;
    int c = lane % CDIM;
    float wL = spatial_decay[c] * (1.0f / (float)TDIM) * (float)CHL;

    float p = 0.f, q = 0.f, o = -1e38f;
#pragma unroll
    for (int j = 0; j < NCH; j++) {
        int idx = j * LANES + lane;
        g_ip[idx] = p; g_iq[idx] = q; g_io[idx] = o;
        float cp = g_cp[idx], cq = g_cq[idx], co = g_co[idx];
        float ow = o + wL;
        float no = fmaxf(ow, co);
        float A = __expf(ow - no);
        float B = __expf(co - no);
        p = A * p + B * cp;
        q = A * q + B * cq;
        o = no;
    }
}

__global__ void wkv_p3_kernel(const float* __restrict__ spatial_decay,
                              const float* __restrict__ spatial_first) {
    int idx = blockIdx.x * blockDim.x + threadIdx.x;
    if (idx >= NCH * LANES2) return;
    int chunk = idx / LANES2;
    int l2    = idx % LANES2;
    int c2 = l2 % CD2, b = l2 / CD2;
    int c = c2 * 2;
    const float inv_t = 1.0f / (float)TDIM;
    float ew0 = __expf(spatial_decay[c]     * inv_t);
    float ew1 = __expf(spatial_decay[c + 1] * inv_t);
    float eu0 = __expf(spatial_first[c]     * inv_t);
    float eu1 = __expf(spatial_first[c + 1] * inv_t);

    const __half2* kp = (const __half2*)(g_k16 + ((size_t)b * TDIM + chunk * CHL) * CDIM) + c2;
    const __half2* vp = (const __half2*)(g_v16 + ((size_t)b * TDIM + chunk * CHL) * CDIM) + c2;
    __half2*       yp = (__half2*)(g_y16 + ((size_t)b * TDIM + chunk * CHL) * CDIM) + c2;

    int i0 = chunk * LANES + b * CDIM + c;
    float2 pp = *(const float2*)(g_ip + i0);
    float2 qq = *(const float2*)(g_iq + i0);
    float2 oo = *(const float2*)(g_io + i0);
    // fixed exponent base for the whole chunk; clamp is exact when p=q=0
    float oi0 = fmaxf(oo.x, -30.f);
    float oi1 = fmaxf(oo.y, -30.f);
    float P0 = pp.x, Q0 = qq.x;
    float P1 = pp.y, Q1 = qq.y;

#pragma unroll 4
    for (int t = 0; t < CHL; t++) {
        float2 kf = __half22float2(kp[(size_t)t * CD2]);
        float2 vf = __half22float2(vp[(size_t)t * CD2]);

        float ek0 = __expf(kf.x - oi0);
        float ek1 = __expf(kf.y - oi1);
        float E0 = ek0 * eu0;
        float E1 = ek1 * eu1;
        float y0 = __fdividef(fmaf(E0, vf.x, P0), Q0 + E0);
        float y1 = __fdividef(fmaf(E1, vf.y, P1), Q1 + E1);
        yp[(size_t)t * CD2] = __floats2half2_rn(y0, y1);

        P0 = fmaf(ew0, P0, vf.x * ek0);
        Q0 = fmaf(ew0, Q0, ek0);
        P1 = fmaf(ew1, P1, vf.y * ek1);
        Q1 = fmaf(ew1, Q1, ek1);
    }
}

// ---------------------------------------------------------------------------
// Stage 4: layernorm(y) * sigmoid_r -> z (fp16). Warp per row, 8 rows/block.
// ---------------------------------------------------------------------------
__global__ __launch_bounds__(256)
void ln_gate_kernel(const float* __restrict__ ln_g,
                    const float* __restrict__ ln_b) {
    int wid  = threadIdx.x >> 5;
    int lane = threadIdx.x & 31;
    int row  = blockIdx.x * 8 + wid;
    size_t rbase = (size_t)row * CDIM;
    const uint4* yrow  = (const uint4*)(g_y16  + rbase);
    const uint4* srrow = (const uint4*)(g_sr16 + rbase);

    // 3 x uint4 = 24 halves per lane
    H8 y8[3];
    float yf[24];
    float s = 0.f;
#pragma unroll
    for (int i = 0; i < 3; i++) {
        y8[i].u = yrow[lane + i * 32];
#pragma unroll
        for (int j = 0; j < 4; j++) {
            float2 f2 = __half22float2(y8[i].h2[j]);
            yf[i * 8 + j * 2]     = f2.x;
            yf[i * 8 + j * 2 + 1] = f2.y;
            s += f2.x + f2.y;
        }
    }
#pragma unroll
    for (int off = 16; off > 0; off >>= 1)
        s += __shfl_xor_sync(0xffffffffu, s, off);
    float mu = s * (1.0f / CDIM);

    float ss = 0.f;
#pragma unroll
    for (int i = 0; i < 24; i++) {
        float d = yf[i] - mu;
        ss += d * d;
    }
#pragma unroll
    for (int off = 16; off > 0; off >>= 1)
        ss += __shfl_xor_sync(0xffffffffu, ss, off);
    float rstd = rsqrtf(ss * (1.0f / CDIM) + 1e-5f);

    uint4* zrow = (uint4*)(g_a16[3] + rbase);
#pragma unroll
    for (int i = 0; i < 3; i++) {
        int c0 = (lane + i * 32) * 8;
        H8 sr8; sr8.u = srrow[lane + i * 32];
        H8 zo;
#pragma unroll
        for (int j = 0; j < 4; j++) {
            float2 sr2 = __half22float2(sr8.h2[j]);
            int c = c0 + j * 2;
            float z0 = sr2.x * ((yf[i * 8 + j * 2]     - mu) * rstd * ln_g[c]     + ln_b[c]);
            float z1 = sr2.y * ((yf[i * 8 + j * 2 + 1] - mu) * rstd * ln_g[c + 1] + ln_b[c + 1]);
            zo.h2[j] = __floats2half2_rn(z0, z1);
        }
        zrow[lane + i * 32] = zo.u;
    }
}

// ---------------------------------------------------------------------------
// Launch: fork-join so the sr GEMM overlaps the WKV chain in the graph.
// ---------------------------------------------------------------------------
extern "C" void kernel_launch(void* const* d_in, const int* in_sizes, int n_in,
                              void* d_out, int out_size) {
    const float* x   = (const float*)d_in[0];
    const float* sd  = (const float*)d_in[3];
    const float* sf  = (const float*)d_in[4];
    const float* mk  = (const float*)d_in[5];
    const float* mv  = (const float*)d_in[6];
    const float* mr  = (const float*)d_in[7];
    const float* Wk  = (const float*)d_in[8];
    const float* Wv  = (const float*)d_in[9];
    const float* Wr  = (const float*)d_in[10];
    const float* Wo  = (const float*)d_in[11];
    const float* lg  = (const float*)d_in[12];
    const float* lb  = (const float*)d_in[13];
    float* out = (float*)d_out;

    cudaFuncSetAttribute(tc_gemm_kernel,
                         cudaFuncAttributeMaxDynamicSharedMemorySize, SM_GEMM);

    // Fork-join resources (created fresh per call; intentionally not destroyed:
    // destroying capture-referenced streams/events mid-capture is illegal, and
    // kernel_launch is invoked only a handful of times).
    cudaStream_t s2;
    cudaStreamCreateWithFlags(&s2, cudaStreamNonBlocking);
    cudaEvent_t eFork, eJoin;
    cudaEventCreateWithFlags(&eFork, cudaEventDisableTiming);
    cudaEventCreateWithFlags(&eJoin, cudaEventDisableTiming);

    // 0. transpose weights -> fp16
    {
        dim3 blk(32, 8);
        dim3 grd(CDIM / 32, CDIM / 32, 4);
        wtrans_kernel<<<grd, blk>>>(Wk, Wv, Wr, Wo);
    }

    // 1. q_shift + mixes -> fp16 (8 channels/thread)
    {
        int n8 = (int)(NELEM / 8);
        shift_mix_kernel<<<(n8 + 255) / 256, 256>>>(x, mk, mv, mr);
    }

    // 2a. k / v GEMMs (z = 0,1) on the main stream
    {
        dim3 gg(CDIM / 128, MROWS / 128, 2);
        tc_gemm_kernel<<<gg, 256, SM_GEMM>>>(-1, nullptr);
    }

    // Fork: sr GEMM runs on s2, concurrent with the WKV chain below.
    cudaEventRecord(eFork, 0);
    cudaStreamWaitEvent(s2, eFork, 0);
    {
        dim3 gg(CDIM / 128, MROWS / 128, 1);
        tc_gemm_kernel<<<gg, 256, SM_GEMM, s2>>>(2, nullptr);
    }
    cudaEventRecord(eJoin, s2);

    // 3. WKV chunked scan on the main stream (needs only k, v)
    wkv_p1_kernel<<<(NCH * LANES2) / 256, 256>>>(sd);
    wkv_p2_kernel<<<(LANES + 255) / 256, 256>>>(sd);
    wkv_p3_kernel<<<(NCH * LANES2) / 256, 256>>>(sd, sf);

    // Join: ln_gate needs sr
    cudaStreamWaitEvent(0, eJoin, 0);

    // 4. layernorm + gate -> z (fp16)
    ln_gate_kernel<<<MROWS / 8, 256>>>(lg, lb);

    // 5. output projection -> d_out
    {
        dim3 gg(CDIM / 128, MROWS / 128, 1);
        tc_gemm_kernel<<<gg, 256, SM_GEMM>>>(3, out);
    }
}

// round 16
// speedup vs baseline: 1.0706x; 1.0077x over previous
#include <cuda_runtime.h>
#include <cuda_fp16.h>
#include <stdint.h>
#include <math.h>

// Problem constants (fixed by dataset: x is (16, 1024, 768), h=w=32)
#define BDIM 16
#define HDIM 32
#define WDIM 32
#define TDIM (HDIM * WDIM)          // 1024
#define CDIM 768
#define MROWS (BDIM * TDIM)         // 16384
#define QC (CDIM / 4)               // 192

#define NELEM ((size_t)MROWS * CDIM)   // 12,582,912

// WKV chunked-scan config (FROZEN: round-10 optimum)
#define LANES (BDIM * CDIM)         // 12288
#define NCH 32
#define CHL (TDIM / NCH)            // 32

// ---------------------------------------------------------------------------
// Scratch (device globals; no allocation allowed)
// ---------------------------------------------------------------------------
__device__ __half g_a16[4][NELEM];              // 0=xk 1=xv 2=xr 3=z (fp16)
__device__ __half g_wh[4][CDIM * CDIM];         // W^T [N][K] fp16
__device__ __half g_k16[NELEM];
__device__ __half g_v16[NELEM];
__device__ __half g_sr16[NELEM];
__device__ __half g_y16[NELEM];
// wkv chunk-local states and per-chunk initial states
__device__ float g_cp[NCH * LANES], g_cq[NCH * LANES], g_co[NCH * LANES];
__device__ float g_ip[NCH * LANES], g_iq[NCH * LANES], g_io[NCH * LANES];

// ---------------------------------------------------------------------------
// PTX helpers (base sm_103-compatible: mma.sync / ldmatrix / cp.async)
// ---------------------------------------------------------------------------
__device__ __forceinline__ uint32_t smem_u32(const void* p) {
    uint32_t a;
    asm("{ .reg .u64 t; cvta.to.shared.u64 t, %1; cvt.u32.u64 %0, t; }"
        : "=r"(a) : "l"(p));
    return a;
}

__device__ __forceinline__ void ldsm4(uint32_t& r0, uint32_t& r1,
                                      uint32_t& r2, uint32_t& r3, uint32_t addr) {
    asm volatile("ldmatrix.sync.aligned.m8n8.x4.shared.b16 {%0,%1,%2,%3}, [%4];"
                 : "=r"(r0), "=r"(r1), "=r"(r2), "=r"(r3) : "r"(addr));
}

__device__ __forceinline__ void mma16816(float* c, const uint32_t* a, const uint32_t* b) {
    asm volatile(
        "mma.sync.aligned.m16n8k16.row.col.f32.f16.f16.f32 "
        "{%0,%1,%2,%3}, {%4,%5,%6,%7}, {%8,%9}, {%0,%1,%2,%3};"
        : "+f"(c[0]), "+f"(c[1]), "+f"(c[2]), "+f"(c[3])
        : "r"(a[0]), "r"(a[1]), "r"(a[2]), "r"(a[3]), "r"(b[0]), "r"(b[1]));
}

__device__ __forceinline__ void cp16(uint32_t saddr, const void* gptr) {
    asm volatile("cp.async.cg.shared.global [%0], [%1], 16;"
                 :: "r"(saddr), "l"(gptr));
}
#define CP_COMMIT() asm volatile("cp.async.commit_group;" ::: "memory")
#define CP_WAIT2()  asm volatile("cp.async.wait_group 2;" ::: "memory")

// ---------------------------------------------------------------------------
// Stage 0: weight transpose + fp16:  Wt[n][k] = W[k][n]
// ---------------------------------------------------------------------------
__global__ void wtrans_kernel(const float* __restrict__ W0, const float* __restrict__ W1,
                              const float* __restrict__ W2, const float* __restrict__ W3) {
    __shared__ float s[32][33];
    const float* W = (blockIdx.z == 0) ? W0 : (blockIdx.z == 1) ? W1
                   : (blockIdx.z == 2) ? W2 : W3;
    int n0 = blockIdx.x * 32, k0 = blockIdx.y * 32;
    int tx = threadIdx.x, ty = threadIdx.y;   // 32 x 8
#pragma unroll
    for (int i = 0; i < 4; i++) {
        int kk = ty + i * 8;
        s[kk][tx] = W[(size_t)(k0 + kk) * CDIM + n0 + tx];
    }
    __syncthreads();
#pragma unroll
    for (int i = 0; i < 4; i++) {
        int nn = ty + i * 8;
        float v = s[tx][nn];                  // = W[k0+tx][n0+nn]
        g_wh[blockIdx.z][(size_t)(n0 + nn) * CDIM + k0 + tx] = __float2half(v);
    }
}

// ---------------------------------------------------------------------------
// Stage 1: q_shift + token mixes -> fp16 (xk, xv, xr), 8 channels/thread
// ---------------------------------------------------------------------------
union H4 { __half h[4]; __half2 h2[2]; uint2 u; };
union H8 { __half h[8]; __half2 h2[4]; uint4 u; };

__device__ __forceinline__ void store_h8(int sel, size_t base,
                                         const float* v) {
    H8 o;
#pragma unroll
    for (int j = 0; j < 4; j++)
        o.h2[j] = __floats2half2_rn(v[j * 2], v[j * 2 + 1]);
    *(uint4*)(&g_a16[sel][base]) = o.u;
}

__global__ void shift_mix_kernel(const float* __restrict__ x,
                                 const float* __restrict__ mix_k,
                                 const float* __restrict__ mix_v,
                                 const float* __restrict__ mix_r) {
    int idx8 = blockIdx.x * blockDim.x + threadIdx.x;
    if (idx8 >= (int)(NELEM / 8)) return;
    int cq = idx8 % (CDIM / 8);
    int sp = idx8 / (CDIM / 8);
    int c  = cq * 8;
    size_t base = (size_t)sp * CDIM + c;
    int wq = sp % WDIM;
    int hq = (sp / WDIM) % HDIM;

    float xx[8] = {0.f, 0.f, 0.f, 0.f, 0.f, 0.f, 0.f, 0.f};
    int g = c / QC;                           // QC=192 divisible by 8
    long long soff = 0; bool have = false;
    if (g == 0)       { have = (wq > 0);        soff = -(long long)CDIM; }
    else if (g == 1)  { have = (wq < WDIM - 1); soff =  (long long)CDIM; }
    else if (g == 2)  { have = (hq > 0);        soff = -(long long)WDIM * CDIM; }
    else              { have = (hq < HDIM - 1); soff =  (long long)WDIM * CDIM; }
    if (have) {
        float4 a = *(const float4*)(x + base + soff);
        float4 b = *(const float4*)(x + base + soff + 4);
        xx[0] = a.x; xx[1] = a.y; xx[2] = a.z; xx[3] = a.w;
        xx[4] = b.x; xx[5] = b.y; xx[6] = b.z; xx[7] = b.w;
    }

    float xc[8], mk[8], mv[8], mr[8];
    {
        float4 a = *(const float4*)(x + base);
        float4 b = *(const float4*)(x + base + 4);
        xc[0] = a.x; xc[1] = a.y; xc[2] = a.z; xc[3] = a.w;
        xc[4] = b.x; xc[5] = b.y; xc[6] = b.z; xc[7] = b.w;
        float4 p = *(const float4*)(mix_k + c);
        float4 q = *(const float4*)(mix_k + c + 4);
        mk[0] = p.x; mk[1] = p.y; mk[2] = p.z; mk[3] = p.w;
        mk[4] = q.x; mk[5] = q.y; mk[6] = q.z; mk[7] = q.w;
        p = *(const float4*)(mix_v + c);
        q = *(const float4*)(mix_v + c + 4);
        mv[0] = p.x; mv[1] = p.y; mv[2] = p.z; mv[3] = p.w;
        mv[4] = q.x; mv[5] = q.y; mv[6] = q.z; mv[7] = q.w;
        p = *(const float4*)(mix_r + c);
        q = *(const float4*)(mix_r + c + 4);
        mr[0] = p.x; mr[1] = p.y; mr[2] = p.z; mr[3] = p.w;
        mr[4] = q.x; mr[5] = q.y; mr[6] = q.z; mr[7] = q.w;
    }

    float vk[8], vv[8], vr[8];
#pragma unroll
    for (int j = 0; j < 8; j++) {
        vk[j] = xc[j] * mk[j] + xx[j] * (1.f - mk[j]);
        vv[j] = xc[j] * mv[j] + xx[j] * (1.f - mv[j]);
        vr[j] = xc[j] * mr[j] + xx[j] * (1.f - mr[j]);
    }
    store_h8(0, base, vk);
    store_h8(1, base, vv);
    store_h8(2, base, vr);
}

// ---------------------------------------------------------------------------
// Stage 2/5: fp16 tensor-core GEMM via mma.sync (single pass).
// CTA tile 128x128, FOUR warps (2x2 -> 64x64 each), BK=32, 4-stage cp.async,
// XOR-swizzled 64B-pitch smem, one __syncthreads per k-iter, 2 CTAs/SM.
// 64x64 warp tiles cut ldsm redundancy 24KB -> 16KB per k16 per CTA.
// ---------------------------------------------------------------------------
#define TILEB 8192                         // 128 rows * 64B
#define STAGEB (2 * TILEB)                 // 16384: [A | Wh]
#define NSTAGE 4
#define SM_GEMM (NSTAGE * STAGEB)          // 65536

__device__ __forceinline__ uint32_t swz_off(int row, int cc) {
    return (uint32_t)(row * 64 + ((cc ^ ((row >> 1) & 3)) << 4));
}

__global__ __launch_bounds__(128, 2)
void tc_gemm_kernel(int aSel, float* __restrict__ cOut) {
    extern __shared__ char smem[];
    const uint32_t sb = smem_u32(smem);
    const int tid = threadIdx.x;
    const int w = tid >> 5, l = tid & 31;
    const int wm = w >> 1, wn = w & 1;

    const int s = (aSel < 0) ? (int)blockIdx.z : aSel;

    const __half* __restrict__ A  = g_a16[s];
    const __half* __restrict__ Wh = g_wh[s];

    const int mrow0 = blockIdx.y * 128;
    const int ncol0 = blockIdx.x * 128;

    float acc[4][8][4];
#pragma unroll
    for (int i = 0; i < 4; i++)
#pragma unroll
        for (int j = 0; j < 8; j++)
#pragma unroll
            for (int q = 0; q < 4; q++) acc[i][j][q] = 0.0f;

    auto issue = [&](int kc, int st) {
        if (kc < 24) {
            uint32_t s0 = sb + st * STAGEB;
#pragma unroll
            for (int j = 0; j < 4; j++) {
                int id = tid + j * 128;          // 0..511
                int row = id >> 2, cc = id & 3;
                size_t gA = (size_t)(mrow0 + row) * CDIM + kc * 32 + cc * 8;
                size_t gB = (size_t)(ncol0 + row) * CDIM + kc * 32 + cc * 8;
                uint32_t so = swz_off(row, cc);
                cp16(s0 + 0 * TILEB + so, A  + gA);
                cp16(s0 + 1 * TILEB + so, Wh + gB);
            }
        }
        CP_COMMIT();
    };

    issue(0, 0); issue(1, 1); issue(2, 2);

    // per-lane ldmatrix row / chunk invariants
    const int aRow = wm * 64 + (l & 15);
    const int aC0  = l >> 4;                    // 0..1
    const int aSwz = (aRow >> 1) & 3;
    const int bRow = wn * 64 + ((l & 7) | ((l >> 4) << 3));
    const int bC0  = (l >> 3) & 1;
    const int bSwz = (bRow >> 1) & 3;

    for (int kc = 0; kc < 24; kc++) {
        int st = kc & 3;
        CP_WAIT2();
        __syncthreads();
        issue(kc + 3, (kc + 3) & 3);
        uint32_t s0 = sb + st * STAGEB;
#pragma unroll
        for (int ks = 0; ks < 2; ks++) {
            uint32_t a[4][4], bh[4][4];
            uint32_t aA = s0 + aRow * 64 + (((aC0 + ks * 2) ^ aSwz) << 4);
            uint32_t bA = s0 + TILEB + bRow * 64 + (((bC0 + ks * 2) ^ bSwz) << 4);
#pragma unroll
            for (int am = 0; am < 4; am++)
                ldsm4(a[am][0], a[am][1], a[am][2], a[am][3],
                      aA + am * 1024);                       // +16 rows
#pragma unroll
            for (int bn = 0; bn < 4; bn++)
                ldsm4(bh[bn][0], bh[bn][1], bh[bn][2], bh[bn][3],
                      bA + bn * 1024);
#pragma unroll
            for (int am = 0; am < 4; am++)
#pragma unroll
                for (int an = 0; an < 8; an++)
                    mma16816(acc[am][an], a[am], &bh[an >> 1][(an & 1) * 2]);
        }
    }

    // Epilogue. s==0/1/2 -> fp16 k/v/sr (sigmoid for s==2); s==3 -> fp32 out.
    if (s <= 2) {
        __half* __restrict__ Ch = (s == 0) ? g_k16 : (s == 1) ? g_v16 : g_sr16;
        const bool sig = (s == 2);
#pragma unroll
        for (int am = 0; am < 4; am++) {
            int r0 = mrow0 + wm * 64 + am * 16 + (l >> 2);
#pragma unroll
            for (int an = 0; an < 8; an++) {
                int cc = ncol0 + wn * 64 + an * 8 + (l & 3) * 2;
                float v0 = acc[am][an][0], v1 = acc[am][an][1];
                float v2 = acc[am][an][2], v3 = acc[am][an][3];
                if (sig) {
                    v0 = 1.0f / (1.0f + __expf(-v0));
                    v1 = 1.0f / (1.0f + __expf(-v1));
                    v2 = 1.0f / (1.0f + __expf(-v2));
                    v3 = 1.0f / (1.0f + __expf(-v3));
                }
                *(__half2*)(Ch + (size_t)r0 * CDIM + cc) =
                    __floats2half2_rn(v0, v1);
                *(__half2*)(Ch + (size_t)(r0 + 8) * CDIM + cc) =
                    __floats2half2_rn(v2, v3);
            }
        }
    } else {
#pragma unroll
        for (int am = 0; am < 4; am++) {
            int r0 = mrow0 + wm * 64 + am * 16 + (l >> 2);
#pragma unroll
            for (int an = 0; an < 8; an++) {
                int cc = ncol0 + wn * 64 + an * 8 + (l & 3) * 2;
                *(float2*)(cOut + (size_t)r0 * CDIM + cc) =
                    make_float2(acc[am][an][0], acc[am][an][1]);
                *(float2*)(cOut + (size_t)(r0 + 8) * CDIM + cc) =
                    make_float2(acc[am][an][2], acc[am][an][3]);
            }
        }
    }
}

// ---------------------------------------------------------------------------
// Stage 3: WKV 3-phase chunked scan, fp16 k/v, ILP-2, fixed-base exponents.
// ---------------------------------------------------------------------------
#define CD2 (CDIM / 2)
#define LANES2 (LANES / 2)

__global__ void wkv_p1_kernel(const float* __restrict__ spatial_decay) {
    int idx = blockIdx.x * blockDim.x + threadIdx.x;   // 0..NCH*LANES2-1
    if (idx >= NCH * LANES2) return;
    int chunk = idx / LANES2;
    int l2    = idx % LANES2;
    int c2 = l2 % CD2, b = l2 / CD2;
    int c = c2 * 2;
    const float inv_t = 1.0f / (float)TDIM;
    float ew0 = __expf(spatial_decay[c]     * inv_t);
    float ew1 = __expf(spatial_decay[c + 1] * inv_t);

    const __half2* kp = (const __half2*)(g_k16 + ((size_t)b * TDIM + chunk * CHL) * CDIM) + c2;
    const __half2* vp = (const __half2*)(g_v16 + ((size_t)b * TDIM + chunk * CHL) * CDIM) + c2;

    // unnormalized chunk-local state (o == 0)
    float p0 = 0.f, q0 = 0.f;
    float p1 = 0.f, q1 = 0.f;
#pragma unroll 4
    for (int t = 0; t < CHL; t++) {
        float2 kf = __half22float2(kp[(size_t)t * CD2]);
        float2 vf = __half22float2(vp[(size_t)t * CD2]);
        float e0 = __expf(kf.x);
        float e1 = __expf(kf.y);
        p0 = fmaf(ew0, p0, vf.x * e0);
        q0 = fmaf(ew0, q0, e0);
        p1 = fmaf(ew1, p1, vf.y * e1);
        q1 = fmaf(ew1, q1, e1);
    }

    int i0 = chunk * LANES + b * CDIM + c;
    *(float2*)(g_cp + i0) = make_float2(p0, p1);
    *(float2*)(g_cq + i0) = make_float2(q0, q1);
    *(float2*)(g_co + i0) = make_float2(0.f, 0.f);
}

__global__ void wkv_p2_kernel(const float* __restrict__ spatial_decay) {
    int lane = blockIdx.x * blockDim.x + threadIdx.x;
    if (lane >= LANES) return;
    int c = lane % CDIM;
    float wL = spatial_decay[c] * (1.0f / (float)TDIM) * (float)CHL;

    float p = 0.f, q = 0.f, o = -1e38f;
#pragma unroll
    for (int j = 0; j < NCH; j++) {
        int idx = j * LANES + lane;
        g_ip[idx] = p; g_iq[idx] = q; g_io[idx] = o;
        float cp = g_cp[idx], cq = g_cq[idx], co = g_co[idx];
        float ow = o + wL;
        float no = fmaxf(ow, co);
        float A = __expf(ow - no);
        float B = __expf(co - no);
        p = A * p + B * cp;
        q = A * q + B * cq;
        o = no;
    }
}

__global__ void wkv_p3_kernel(const float* __restrict__ spatial_decay,
                              const float* __restrict__ spatial_first) {
    int idx = blockIdx.x * blockDim.x + threadIdx.x;
    if (idx >= NCH * LANES2) return;
    int chunk = idx / LANES2;
    int l2    = idx % LANES2;
    int c2 = l2 % CD2, b = l2 / CD2;
    int c = c2 * 2;
    const float inv_t = 1.0f / (float)TDIM;
    float ew0 = __expf(spatial_decay[c]     * inv_t);
    float ew1 = __expf(spatial_decay[c + 1] * inv_t);
    float eu0 = __expf(spatial_first[c]     * inv_t);
    float eu1 = __expf(spatial_first[c + 1] * inv_t);

    const __half2* kp = (const __half2*)(g_k16 + ((size_t)b * TDIM + chunk * CHL) * CDIM) + c2;
    const __half2* vp = (const __half2*)(g_v16 + ((size_t)b * TDIM + chunk * CHL) * CDIM) + c2;
    __half2*       yp = (__half2*)(g_y16 + ((size_t)b * TDIM + chunk * CHL) * CDIM) + c2;

    int i0 = chunk * LANES + b * CDIM + c;
    float2 pp = *(const float2*)(g_ip + i0);
    float2 qq = *(const float2*)(g_iq + i0);
    float2 oo = *(const float2*)(g_io + i0);
    // fixed exponent base for the whole chunk; clamp is exact when p=q=0
    float oi0 = fmaxf(oo.x, -30.f);
    float oi1 = fmaxf(oo.y, -30.f);
    float P0 = pp.x, Q0 = qq.x;
    float P1 = pp.y, Q1 = qq.y;

#pragma unroll 4
    for (int t = 0; t < CHL; t++) {
        float2 kf = __half22float2(kp[(size_t)t * CD2]);
        float2 vf = __half22float2(vp[(size_t)t * CD2]);

        float ek0 = __expf(kf.x - oi0);
        float ek1 = __expf(kf.y - oi1);
        float E0 = ek0 * eu0;
        float E1 = ek1 * eu1;
        float y0 = __fdividef(fmaf(E0, vf.x, P0), Q0 + E0);
        float y1 = __fdividef(fmaf(E1, vf.y, P1), Q1 + E1);
        yp[(size_t)t * CD2] = __floats2half2_rn(y0, y1);

        P0 = fmaf(ew0, P0, vf.x * ek0);
        Q0 = fmaf(ew0, Q0, ek0);
        P1 = fmaf(ew1, P1, vf.y * ek1);
        Q1 = fmaf(ew1, Q1, ek1);
    }
}

// ---------------------------------------------------------------------------
// Stage 4: layernorm(y) * sigmoid_r -> z (fp16). Warp per row, 8 rows/block.
// ---------------------------------------------------------------------------
__global__ __launch_bounds__(256)
void ln_gate_kernel(const float* __restrict__ ln_g,
                    const float* __restrict__ ln_b) {
    int wid  = threadIdx.x >> 5;
    int lane = threadIdx.x & 31;
    int row  = blockIdx.x * 8 + wid;
    size_t rbase = (size_t)row * CDIM;
    const uint4* yrow  = (const uint4*)(g_y16  + rbase);
    const uint4* srrow = (const uint4*)(g_sr16 + rbase);

    // 3 x uint4 = 24 halves per lane
    H8 y8[3];
    float yf[24];
    float s = 0.f;
#pragma unroll
    for (int i = 0; i < 3; i++) {
        y8[i].u = yrow[lane + i * 32];
#pragma unroll
        for (int j = 0; j < 4; j++) {
            float2 f2 = __half22float2(y8[i].h2[j]);
            yf[i * 8 + j * 2]     = f2.x;
            yf[i * 8 + j * 2 + 1] = f2.y;
            s += f2.x + f2.y;
        }
    }
#pragma unroll
    for (int off = 16; off > 0; off >>= 1)
        s += __shfl_xor_sync(0xffffffffu, s, off);
    float mu = s * (1.0f / CDIM);

    float ss = 0.f;
#pragma unroll
    for (int i = 0; i < 24; i++) {
        float d = yf[i] - mu;
        ss += d * d;
    }
#pragma unroll
    for (int off = 16; off > 0; off >>= 1)
        ss += __shfl_xor_sync(0xffffffffu, ss, off);
    float rstd = rsqrtf(ss * (1.0f / CDIM) + 1e-5f);

    uint4* zrow = (uint4*)(g_a16[3] + rbase);
#pragma unroll
    for (int i = 0; i < 3; i++) {
        int c0 = (lane + i * 32) * 8;
        H8 sr8; sr8.u = srrow[lane + i * 32];
        H8 zo;
#pragma unroll
        for (int j = 0; j < 4; j++) {
            float2 sr2 = __half22float2(sr8.h2[j]);
            int c = c0 + j * 2;
            float z0 = sr2.x * ((yf[i * 8 + j * 2]     - mu) * rstd * ln_g[c]     + ln_b[c]);
            float z1 = sr2.y * ((yf[i * 8 + j * 2 + 1] - mu) * rstd * ln_g[c + 1] + ln_b[c + 1]);
            zo.h2[j] = __floats2half2_rn(z0, z1);
        }
        zrow[lane + i * 32] = zo.u;
    }
}

// ---------------------------------------------------------------------------
// Launch: fork-join so the sr GEMM overlaps the WKV chain in the graph.
// ---------------------------------------------------------------------------
extern "C" void kernel_launch(void* const* d_in, const int* in_sizes, int n_in,
                              void* d_out, int out_size) {
    const float* x   = (const float*)d_in[0];
    const float* sd  = (const float*)d_in[3];
    const float* sf  = (const float*)d_in[4];
    const float* mk  = (const float*)d_in[5];
    const float* mv  = (const float*)d_in[6];
    const float* mr  = (const float*)d_in[7];
    const float* Wk  = (const float*)d_in[8];
    const float* Wv  = (const float*)d_in[9];
    const float* Wr  = (const float*)d_in[10];
    const float* Wo  = (const float*)d_in[11];
    const float* lg  = (const float*)d_in[12];
    const float* lb  = (const float*)d_in[13];
    float* out = (float*)d_out;

    cudaFuncSetAttribute(tc_gemm_kernel,
                         cudaFuncAttributeMaxDynamicSharedMemorySize, SM_GEMM);

    // Fork-join resources (created fresh per call; intentionally not destroyed:
    // destroying capture-referenced streams/events mid-capture is illegal, and
    // kernel_launch is invoked only a handful of times).
    cudaStream_t s2;
    cudaStreamCreateWithFlags(&s2, cudaStreamNonBlocking);
    cudaEvent_t eFork, eJoin;
    cudaEventCreateWithFlags(&eFork, cudaEventDisableTiming);
    cudaEventCreateWithFlags(&eJoin, cudaEventDisableTiming);

    // 0. transpose weights -> fp16
    {
        dim3 blk(32, 8);
        dim3 grd(CDIM / 32, CDIM / 32, 4);
        wtrans_kernel<<<grd, blk>>>(Wk, Wv, Wr, Wo);
    }

    // 1. q_shift + mixes -> fp16 (8 channels/thread)
    {
        int n8 = (int)(NELEM / 8);
        shift_mix_kernel<<<(n8 + 255) / 256, 256>>>(x, mk, mv, mr);
    }

    // 2a. k / v GEMMs (z = 0,1) on the main stream
    {
        dim3 gg(CDIM / 128, MROWS / 128, 2);
        tc_gemm_kernel<<<gg, 128, SM_GEMM>>>(-1, nullptr);
    }

    // Fork: sr GEMM runs on s2, concurrent with the WKV chain below.
    cudaEventRecord(eFork, 0);
    cudaStreamWaitEvent(s2, eFork, 0);
    {
        dim3 gg(CDIM / 128, MROWS / 128, 1);
        tc_gemm_kernel<<<gg, 128, SM_GEMM, s2>>>(2, nullptr);
    }
    cudaEventRecord(eJoin, s2);

    // 3. WKV chunked scan on the main stream (needs only k, v)
    wkv_p1_kernel<<<(NCH * LANES2) / 256, 256>>>(sd);
    wkv_p2_kernel<<<(LANES + 255) / 256, 256>>>(sd);
    wkv_p3_kernel<<<(NCH * LANES2) / 256, 256>>>(sd, sf);

    // Join: ln_gate needs sr
    cudaStreamWaitEvent(0, eJoin, 0);

    // 4. layernorm + gate -> z (fp16)
    ln_gate_kernel<<<MROWS / 8, 256>>>(lg, lb);

    // 5. output projection -> d_out
    {
        dim3 gg(CDIM / 128, MROWS / 128, 1);
        tc_gemm_kernel<<<gg, 128, SM_GEMM>>>(3, out);
    }
}